// round 2
// baseline (speedup 1.0000x reference)
#include <cuda_runtime.h>
#include <math.h>

#define BATCH 4
#define SEQ 2048
#define DIM 128
#define QH 16
#define KVH 4
#define WINDOW 512

typedef unsigned long long u64;

// ---- packed f32x2 helpers (FFMA2 is only reachable via PTX fma.rn.f32x2) ----
__device__ __forceinline__ u64 pk2(float lo, float hi) {
    u64 r; asm("mov.b64 %0,{%1,%2};" : "=l"(r) : "f"(lo), "f"(hi)); return r;
}
__device__ __forceinline__ void upk2(u64 v, float& lo, float& hi) {
    asm("mov.b64 {%0,%1},%2;" : "=f"(lo), "=f"(hi) : "l"(v));
}
__device__ __forceinline__ void fma2(u64& d, u64 a, u64 b) {
    asm("fma.rn.f32x2 %0,%1,%2,%0;" : "+l"(d) : "l"(a), "l"(b));
}
__device__ __forceinline__ u64 mul2(u64 a, u64 b) {
    u64 d; asm("mul.rn.f32x2 %0,%1,%2;" : "=l"(d) : "l"(a), "l"(b)); return d;
}
__device__ __forceinline__ u64 lds2(const float* p) {
    return *reinterpret_cast<const u64*>(p);
}

// Scratch (device globals: allocation-free)
__device__ float g_Q[BATCH * QH * SEQ * DIM];   // [b][h][s][d], pre-scaled by scale*log2e
__device__ float g_K[BATCH * KVH * SEQ * DIM];  // [b][g][s][d]
__device__ float g_V[BATCH * KVH * SEQ * DIM];  // [b][g][s][d]
__device__ float g_A[BATCH * SEQ * QH * DIM];   // [b][s][h*128+d]

// ---------------------------------------------------------------------------
// Kernel A: qkv = x @ W_qkv, scatter into g_Q/g_K/g_V.
// Block tile 64x128 (one full head per block). 256 threads.
// Rows: ty+16i (i<4). Cols: 2*tx+32*j (j<4) -> f32x2 pairs.
// ---------------------------------------------------------------------------
__global__ void __launch_bounds__(256) qkv_kernel(const float* __restrict__ x,
                                                  const float* __restrict__ Wqkv) {
    __shared__ float Xs[64 * 66];    // [m][k]
    __shared__ float Ws[64 * 130];   // [k][n]
    const int m0 = blockIdx.x * 64;
    const int head = blockIdx.y;     // 0..23
    const int n0 = head * 128;
    const int tid = threadIdx.x;
    const int ty = tid >> 4;
    const int tx = tid & 15;

    u64 acc[4][4] = {};

    for (int k0 = 0; k0 < 128; k0 += 64) {
        // X tile 64x64 (u64 elements: 2048)
        for (int idx = tid; idx < 2048; idx += 256) {
            int r = idx >> 5, c = (idx & 31) * 2;
            *reinterpret_cast<u64*>(&Xs[r * 66 + c]) =
                *reinterpret_cast<const u64*>(&x[(m0 + r) * 128 + k0 + c]);
        }
        // W tile 64x128 (u64 elements: 4096)
        for (int idx = tid; idx < 4096; idx += 256) {
            int r = idx >> 6, c = (idx & 63) * 2;
            *reinterpret_cast<u64*>(&Ws[r * 130 + c]) =
                *reinterpret_cast<const u64*>(&Wqkv[(k0 + r) * 3072 + n0 + c]);
        }
        __syncthreads();
#pragma unroll 8
        for (int k = 0; k < 64; k++) {
            u64 a2[4], w2[4];
#pragma unroll
            for (int i = 0; i < 4; i++) {
                float a = Xs[(ty + 16 * i) * 66 + k];
                a2[i] = pk2(a, a);
            }
#pragma unroll
            for (int j = 0; j < 4; j++) w2[j] = lds2(&Ws[k * 130 + 2 * tx + 32 * j]);
#pragma unroll
            for (int i = 0; i < 4; i++)
#pragma unroll
                for (int j = 0; j < 4; j++) fma2(acc[i][j], a2[i], w2[j]);
        }
        __syncthreads();
    }

    const float qs = 1.4426950408889634f * 0.08838834764831845f; // log2e/sqrt(128)
    const u64 qs2 = pk2(qs, qs);

    float* dst;
    bool do_scale = false;
    if (head < QH) { dst = g_Q; do_scale = true; }
    else if (head < QH + KVH) { dst = g_K; }
    else { dst = g_V; }
    const int hh = (head < QH) ? head : (head < QH + KVH ? head - QH : head - QH - KVH);
    const int nheads = (head < QH) ? QH : KVH;

#pragma unroll
    for (int i = 0; i < 4; i++) {
        int m = m0 + ty + 16 * i;
        int b = m >> 11, s = m & 2047;
        float* row = dst + ((long)(b * nheads + hh) * SEQ + s) * DIM;
#pragma unroll
        for (int j = 0; j < 4; j++) {
            u64 v = acc[i][j];
            if (do_scale) v = mul2(v, qs2);
            *reinterpret_cast<u64*>(&row[2 * tx + 32 * j]) = v;
        }
    }
}

// ---------------------------------------------------------------------------
// Kernel B: windowed-causal flash attention with ALiBi (exp2 domain), FFMA2.
// Block = (q-tile 64, head, batch); 256 threads.
// S tile: rows ty+16i (i<4), cols tx+16j (j<4); accumulated packed over k.
// O tile: rows ty+16i (i<4), cols 2*tx+32*c (c<4) as f32x2 pairs.
// ---------------------------------------------------------------------------
#define QSTR 130
#define PSTR 66

__global__ void __launch_bounds__(256) attn_kernel() {
    extern __shared__ float sm[];
    float* Qs = sm;                 // [64][QSTR]
    float* Ks = Qs + 64 * QSTR;     // [64][QSTR]
    float* Vs = Ks + 64 * QSTR;     // [64][QSTR]
    float* Ps = Vs + 64 * QSTR;     // [64][PSTR]

    const int qt = blockIdx.x;
    const int h  = blockIdx.y;
    const int b  = blockIdx.z;
    const int g  = h >> 2;
    const float slope2 = exp2f(-(float)(h + 1) * 0.5f) * 1.4426950408889634f;

    const int tid = threadIdx.x;
    const int ty = tid >> 4;
    const int tx = tid & 15;

    const float* Qg = g_Q + ((b * QH + h) * SEQ + qt * 64) * DIM;
    const float* Kg = g_K + (b * KVH + g) * SEQ * DIM;
    const float* Vg = g_V + (b * KVH + g) * SEQ * DIM;

    // load Q tile (u64 elements: 64*64)
    for (int idx = tid; idx < 4096; idx += 256) {
        int r = idx >> 6, c = (idx & 63) * 2;
        *reinterpret_cast<u64*>(&Qs[r * QSTR + c]) =
            *reinterpret_cast<const u64*>(&Qg[r * 128 + c]);
    }

    float m_i[4], l_i[4];
    u64 acc[4][4] = {};
#pragma unroll
    for (int i = 0; i < 4; i++) { m_i[i] = -1e30f; l_i[i] = 0.0f; }

    const int q0 = qt * 64;
    const int kt0 = (q0 >= WINDOW) ? (q0 - WINDOW) : 0;

    for (int kt = kt0; kt <= q0; kt += 64) {
        __syncthreads();
        for (int idx = tid; idx < 4096; idx += 256) {
            int r = idx >> 6, c = (idx & 63) * 2;
            *reinterpret_cast<u64*>(&Ks[r * QSTR + c]) =
                *reinterpret_cast<const u64*>(&Kg[(kt + r) * 128 + c]);
            *reinterpret_cast<u64*>(&Vs[r * QSTR + c]) =
                *reinterpret_cast<const u64*>(&Vg[(kt + r) * 128 + c]);
        }
        __syncthreads();

        // --- S = Q K^T, packed over k ---
        u64 s2[4][4] = {};
#pragma unroll 4
        for (int k = 0; k < 128; k += 2) {
            u64 a2[4], k2[4];
#pragma unroll
            for (int i = 0; i < 4; i++) a2[i] = lds2(&Qs[(ty + 16 * i) * QSTR + k]);
#pragma unroll
            for (int j = 0; j < 4; j++) k2[j] = lds2(&Ks[(tx + 16 * j) * QSTR + k]);
#pragma unroll
            for (int i = 0; i < 4; i++)
#pragma unroll
                for (int j = 0; j < 4; j++) fma2(s2[i][j], a2[i], k2[j]);
        }

        float s[4][4];
#pragma unroll
        for (int i = 0; i < 4; i++)
#pragma unroll
            for (int j = 0; j < 4; j++) {
                float lo, hi; upk2(s2[i][j], lo, hi);
                s[i][j] = lo + hi;
            }

        // --- ALiBi + window mask ---
#pragma unroll
        for (int i = 0; i < 4; i++) {
#pragma unroll
            for (int j = 0; j < 4; j++) {
                int q = q0 + ty + 16 * i;
                int kc = kt + tx + 16 * j;
                float val = s[i][j] + slope2 * (float)(q - kc);
                bool valid = (kc <= q) && (q - kc <= WINDOW);
                s[i][j] = valid ? val : -1e30f;
            }
        }

        // --- online softmax update ---
#pragma unroll
        for (int i = 0; i < 4; i++) {
            float mt = s[i][0];
#pragma unroll
            for (int j = 1; j < 4; j++) mt = fmaxf(mt, s[i][j]);
#pragma unroll
            for (int off = 8; off >= 1; off >>= 1)
                mt = fmaxf(mt, __shfl_xor_sync(0xffffffffu, mt, off));
            float mnew = fmaxf(m_i[i], mt);
            float alpha = exp2f(m_i[i] - mnew);
            float psum = 0.0f;
#pragma unroll
            for (int j = 0; j < 4; j++) {
                float p = exp2f(s[i][j] - mnew);
                s[i][j] = p;
                psum += p;
            }
#pragma unroll
            for (int off = 8; off >= 1; off >>= 1)
                psum += __shfl_xor_sync(0xffffffffu, psum, off);
            l_i[i] = l_i[i] * alpha + psum;
            m_i[i] = mnew;
            u64 al2 = pk2(alpha, alpha);
#pragma unroll
            for (int c = 0; c < 4; c++) acc[i][c] = mul2(acc[i][c], al2);
        }

        // --- stage P, then O += P @ V (packed over column pairs) ---
#pragma unroll
        for (int i = 0; i < 4; i++)
#pragma unroll
            for (int j = 0; j < 4; j++)
                Ps[(ty + 16 * i) * PSTR + (tx + 16 * j)] = s[i][j];
        __syncthreads();

#pragma unroll 4
        for (int kk = 0; kk < 64; kk++) {
            u64 pr2[4], v2[4];
#pragma unroll
            for (int i = 0; i < 4; i++) {
                float p = Ps[(ty + 16 * i) * PSTR + kk];
                pr2[i] = pk2(p, p);
            }
#pragma unroll
            for (int c = 0; c < 4; c++) v2[c] = lds2(&Vs[kk * QSTR + 2 * tx + 32 * c]);
#pragma unroll
            for (int i = 0; i < 4; i++)
#pragma unroll
                for (int c = 0; c < 4; c++) fma2(acc[i][c], pr2[i], v2[c]);
        }
    }

    // --- normalize, write att to g_A [b][s][h*128+d] ---
#pragma unroll
    for (int i = 0; i < 4; i++) {
        float inv_l = 1.0f / l_i[i];
        u64 inv2 = pk2(inv_l, inv_l);
        long rowbase = ((long)b * SEQ + (q0 + ty + 16 * i)) * (QH * DIM) + h * DIM;
#pragma unroll
        for (int c = 0; c < 4; c++) {
            *reinterpret_cast<u64*>(&g_A[rowbase + 2 * tx + 32 * c]) = mul2(acc[i][c], inv2);
        }
    }
}

// ---------------------------------------------------------------------------
// Kernel C: out = g_A @ W_proj. M=8192, K=2048, N=128.
// Block: 32 rows x 128 cols, 256 threads. Rows ty+16i (i<2), cols 2*tx+32*c.
// ---------------------------------------------------------------------------
__global__ void __launch_bounds__(256) proj_kernel(const float* __restrict__ Wp,
                                                   float* __restrict__ out) {
    __shared__ float As[32 * 66];
    __shared__ float Ws[64 * 130];
    const int m0 = blockIdx.x * 32;
    const int tid = threadIdx.x;
    const int ty = tid >> 4;
    const int tx = tid & 15;

    u64 acc[2][4] = {};

    for (int k0 = 0; k0 < 2048; k0 += 64) {
        // A tile 32x64 (1024 u64)
        for (int idx = tid; idx < 1024; idx += 256) {
            int r = idx >> 5, c = (idx & 31) * 2;
            *reinterpret_cast<u64*>(&As[r * 66 + c]) =
                *reinterpret_cast<const u64*>(&g_A[(long)(m0 + r) * 2048 + k0 + c]);
        }
        // W tile 64x128 (4096 u64)
        for (int idx = tid; idx < 4096; idx += 256) {
            int r = idx >> 6, c = (idx & 63) * 2;
            *reinterpret_cast<u64*>(&Ws[r * 130 + c]) =
                *reinterpret_cast<const u64*>(&Wp[(k0 + r) * 128 + c]);
        }
        __syncthreads();
#pragma unroll 8
        for (int k = 0; k < 64; k++) {
            u64 a2[2], w2[4];
#pragma unroll
            for (int i = 0; i < 2; i++) {
                float a = As[(ty + 16 * i) * 66 + k];
                a2[i] = pk2(a, a);
            }
#pragma unroll
            for (int c = 0; c < 4; c++) w2[c] = lds2(&Ws[k * 130 + 2 * tx + 32 * c]);
#pragma unroll
            for (int i = 0; i < 2; i++)
#pragma unroll
                for (int c = 0; c < 4; c++) fma2(acc[i][c], a2[i], w2[c]);
        }
        __syncthreads();
    }

#pragma unroll
    for (int i = 0; i < 2; i++)
#pragma unroll
        for (int c = 0; c < 4; c++)
            *reinterpret_cast<u64*>(&out[(m0 + ty + 16 * i) * 128 + 2 * tx + 32 * c]) = acc[i][c];
}

// ---------------------------------------------------------------------------
extern "C" void kernel_launch(void* const* d_in, const int* in_sizes, int n_in,
                              void* d_out, int out_size) {
    const float* x     = (const float*)d_in[0];  // (4, 2048, 128)
    const float* Wqkv  = (const float*)d_in[1];  // (128, 3072)
    const float* Wproj = (const float*)d_in[2];  // (2048, 128)
    float* out = (float*)d_out;                  // (4, 2048, 128)

    qkv_kernel<<<dim3(8192 / 64, 24), 256>>>(x, Wqkv);

    const int attn_smem = (3 * 64 * QSTR + 64 * PSTR) * (int)sizeof(float); // 116736 B
    cudaFuncSetAttribute(attn_kernel, cudaFuncAttributeMaxDynamicSharedMemorySize, attn_smem);
    attn_kernel<<<dim3(32, 16, 4), 256, attn_smem>>>();

    proj_kernel<<<dim3(8192 / 32), 256>>>(Wproj, out);
}

// round 4
// speedup vs baseline: 1.8081x; 1.8081x over previous
#include <cuda_runtime.h>
#include <cuda_bf16.h>
#include <cstdint>
#include <math.h>

#define BATCH 4
#define SEQ 2048
#define DIM 128
#define QH 16
#define KVH 4
#define WINDOW 512

// ---------------------------------------------------------------------------
// device-global scratch (allocation-free)
// ---------------------------------------------------------------------------
__device__ __nv_bfloat16 g_Qh[BATCH * QH * SEQ * DIM];   // pre-scaled by log2e/sqrt(128)
__device__ __nv_bfloat16 g_Ql[BATCH * QH * SEQ * DIM];
__device__ __nv_bfloat16 g_Kh[BATCH * KVH * SEQ * DIM];
__device__ __nv_bfloat16 g_Kl[BATCH * KVH * SEQ * DIM];
__device__ __nv_bfloat16 g_Vh[BATCH * KVH * SEQ * DIM];
__device__ __nv_bfloat16 g_Vl[BATCH * KVH * SEQ * DIM];
__device__ float g_A[BATCH * SEQ * QH * DIM];            // [b][s][h*128+d]

// ---------------------------------------------------------------------------
// base-ISA helpers (sm_80-era: ldmatrix + mma.sync -> HMMA)
// ---------------------------------------------------------------------------
__device__ __forceinline__ uint32_t smem_u32(const void* p) {
    uint32_t a;
    asm("{ .reg .u64 t; cvta.to.shared.u64 t, %1; cvt.u32.u64 %0, t; }" : "=r"(a) : "l"(p));
    return a;
}
__device__ __forceinline__ void ldm_x4(uint32_t* r, uint32_t addr) {
    asm volatile("ldmatrix.sync.aligned.m8n8.x4.shared.b16 {%0,%1,%2,%3},[%4];"
        : "=r"(r[0]), "=r"(r[1]), "=r"(r[2]), "=r"(r[3]) : "r"(addr));
}
__device__ __forceinline__ void ldm_x4t(uint32_t* r, uint32_t addr) {
    asm volatile("ldmatrix.sync.aligned.m8n8.x4.trans.shared.b16 {%0,%1,%2,%3},[%4];"
        : "=r"(r[0]), "=r"(r[1]), "=r"(r[2]), "=r"(r[3]) : "r"(addr));
}
__device__ __forceinline__ void mma_bf16(float* d, const uint32_t* a, const uint32_t* b) {
    asm volatile(
        "mma.sync.aligned.m16n8k16.row.col.f32.bf16.bf16.f32 "
        "{%0,%1,%2,%3},{%4,%5,%6,%7},{%8,%9},{%0,%1,%2,%3};"
        : "+f"(d[0]), "+f"(d[1]), "+f"(d[2]), "+f"(d[3])
        : "r"(a[0]), "r"(a[1]), "r"(a[2]), "r"(a[3]), "r"(b[0]), "r"(b[1]));
}
// pack round-to-nearest bf16x2 from two floats (lo, hi)
__device__ __forceinline__ uint32_t pkbf(float lo, float hi) {
    uint32_t r; asm("cvt.rn.bf16x2.f32 %0,%1,%2;" : "=r"(r) : "f"(hi), "f"(lo)); return r;
}
// bf16 truncation of a float (high 16 bits)
__device__ __forceinline__ float btrunc(float x) {
    return __uint_as_float(__float_as_uint(x) & 0xffff0000u);
}

// ---------------------------------------------------------------------------
// Kernel A: qkv GEMM (fp32 SIMT) -> split-bf16 scatter
// ---------------------------------------------------------------------------
__global__ void __launch_bounds__(256) qkv_kernel(const float* __restrict__ x,
                                                  const float* __restrict__ Wqkv) {
    __shared__ float Xs[64][66];
    __shared__ float Ws[64][66];
    const int m0 = blockIdx.x * 64;
    const int n0 = blockIdx.y * 64;
    const int tid = threadIdx.x;
    const int ty = tid >> 4;
    const int tx = tid & 15;

    float acc[4][4] = {};

    for (int k0 = 0; k0 < 128; k0 += 64) {
        for (int idx = tid; idx < 64 * 64; idx += 256) {
            int r = idx >> 6, c = idx & 63;
            Xs[r][c] = x[(m0 + r) * 128 + (k0 + c)];
        }
        for (int idx = tid; idx < 64 * 64; idx += 256) {
            int r = idx >> 6, c = idx & 63;
            Ws[r][c] = Wqkv[(k0 + r) * 3072 + (n0 + c)];
        }
        __syncthreads();
#pragma unroll 8
        for (int k = 0; k < 64; k++) {
            float a[4], bb[4];
#pragma unroll
            for (int i = 0; i < 4; i++) a[i] = Xs[ty + 16 * i][k];
#pragma unroll
            for (int j = 0; j < 4; j++) bb[j] = Ws[k][tx + 16 * j];
#pragma unroll
            for (int i = 0; i < 4; i++)
#pragma unroll
                for (int j = 0; j < 4; j++) acc[i][j] += a[i] * bb[j];
        }
        __syncthreads();
    }

    const float qscale = 1.4426950408889634f * 0.08838834764831845f; // log2e/sqrt(128)
    const int head = n0 >> 7;
    const int dbase = n0 & 127;

#pragma unroll
    for (int i = 0; i < 4; i++) {
        int m = m0 + ty + 16 * i;
        int b = m >> 11, s = m & 2047;
#pragma unroll
        for (int j = 0; j < 4; j++) {
            int d = dbase + tx + 16 * j;
            float v = acc[i][j];
            __nv_bfloat16 hi; float hf; long o;
            if (head < QH) {
                v *= qscale;
                hi = __float2bfloat16(v); hf = __bfloat162float(hi);
                o = ((long)(b * QH + head) * SEQ + s) * DIM + d;
                g_Qh[o] = hi; g_Ql[o] = __float2bfloat16(v - hf);
            } else if (head < QH + KVH) {
                hi = __float2bfloat16(v); hf = __bfloat162float(hi);
                o = ((long)(b * KVH + (head - QH)) * SEQ + s) * DIM + d;
                g_Kh[o] = hi; g_Kl[o] = __float2bfloat16(v - hf);
            } else {
                hi = __float2bfloat16(v); hf = __bfloat162float(hi);
                o = ((long)(b * KVH + (head - QH - KVH)) * SEQ + s) * DIM + d;
                g_Vh[o] = hi; g_Vl[o] = __float2bfloat16(v - hf);
            }
        }
    }
}

// ---------------------------------------------------------------------------
// Kernel B: flash attention via mma.sync (HMMA bf16, split hi/lo, fp32 accum)
// Block = 64 q-rows x head x batch, 4 warps (each owns 16 rows).
// ---------------------------------------------------------------------------
#define TSTR_B 272                  // smem row stride in bytes (128 bf16 + 8 pad)
#define TILE_B (64 * TSTR_B)        // 17408
#define QHO 0
#define QLO (1 * TILE_B)
#define KHO (2 * TILE_B)
#define KLO (3 * TILE_B)
#define VHO (4 * TILE_B)
#define VLO (5 * TILE_B)
#define ATTN_SMEM (6 * TILE_B)      // 104448

__global__ void __launch_bounds__(128) attn_kernel() {
    extern __shared__ char smc[];
    const uint32_t sb = smem_u32(smc);
    const int tid = threadIdx.x;
    const int lane = tid & 31;
    const int w = tid >> 5;
    const int m0w = w * 16;

    const int qt = blockIdx.x;
    const int h  = blockIdx.y;
    const int b  = blockIdx.z;
    const int g  = h >> 2;
    const int q0 = qt * 64;
    const float slope2 = exp2f(-(float)(h + 1) * 0.5f) * 1.4426950408889634f;

    const __nv_bfloat16* Qhg = g_Qh + ((long)(b * QH + h) * SEQ + q0) * DIM;
    const __nv_bfloat16* Qlg = g_Ql + ((long)(b * QH + h) * SEQ + q0) * DIM;
    const __nv_bfloat16* Khg = g_Kh + (long)(b * KVH + g) * SEQ * DIM;
    const __nv_bfloat16* Klg = g_Kl + (long)(b * KVH + g) * SEQ * DIM;
    const __nv_bfloat16* Vhg = g_Vh + (long)(b * KVH + g) * SEQ * DIM;
    const __nv_bfloat16* Vlg = g_Vl + (long)(b * KVH + g) * SEQ * DIM;

    // load Q tiles (64 x 128 bf16 each, 16B-chunked)
    for (int idx = tid; idx < 1024; idx += 128) {
        int r = idx >> 4, c = idx & 15;
        *(uint4*)(smc + QHO + r * TSTR_B + c * 16) = *(const uint4*)((const char*)Qhg + r * 256 + c * 16);
        *(uint4*)(smc + QLO + r * TSTR_B + c * 16) = *(const uint4*)((const char*)Qlg + r * 256 + c * 16);
    }

    // per-thread softmax state: rows r0 = lane>>2, r1 = r0+8 (within warp's 16)
    float m0r = -1e30f, m1r = -1e30f, l0 = 0.0f, l1 = 0.0f;
    float oacc[16][4];
#pragma unroll
    for (int t = 0; t < 16; t++)
#pragma unroll
        for (int j = 0; j < 4; j++) oacc[t][j] = 0.0f;

    const int qr0 = q0 + m0w + (lane >> 2);
    const int qr1 = qr0 + 8;
    const int ktlo = (q0 >= WINDOW) ? (q0 - WINDOW) : 0;

    // precomputed ldmatrix address offsets (within-tile, byte units)
    const uint32_t aoff = (uint32_t)(m0w + (lane & 15)) * TSTR_B + ((lane >> 4) << 3) * 2;
    const uint32_t boff_n = (uint32_t)(((lane >> 4) << 3) + (lane & 7)) * TSTR_B + (lane & 8) * 2;
    const uint32_t voff_r = (uint32_t)((lane & 8) + (lane & 7)) * TSTR_B + ((lane >> 4) << 3) * 2;

    for (int kt = ktlo; kt < q0 + 64; kt += 64) {
        __syncthreads();
        for (int idx = tid; idx < 1024; idx += 128) {
            int r = idx >> 4, c = idx & 15;
            long go = (long)(kt + r) * 256 + c * 16;
            *(uint4*)(smc + KHO + r * TSTR_B + c * 16) = *(const uint4*)((const char*)Khg + go);
            *(uint4*)(smc + KLO + r * TSTR_B + c * 16) = *(const uint4*)((const char*)Klg + go);
            *(uint4*)(smc + VHO + r * TSTR_B + c * 16) = *(const uint4*)((const char*)Vhg + go);
            *(uint4*)(smc + VLO + r * TSTR_B + c * 16) = *(const uint4*)((const char*)Vlg + go);
        }
        __syncthreads();

        // ---- S = Q K^T (3-term split), 8 n8-tiles per warp ----
        float sacc[8][4];
#pragma unroll
        for (int t = 0; t < 8; t++)
#pragma unroll
            for (int j = 0; j < 4; j++) sacc[t][j] = 0.0f;

#pragma unroll
        for (int ks = 0; ks < 8; ks++) {
            uint32_t ah[4], al[4];
            ldm_x4(ah, sb + QHO + aoff + ks * 32);
            ldm_x4(al, sb + QLO + aoff + ks * 32);
#pragma unroll
            for (int nt = 0; nt < 4; nt++) {
                uint32_t bh[4], bl[4];
                uint32_t bo = boff_n + (uint32_t)(nt * 16) * TSTR_B + ks * 32;
                ldm_x4(bh, sb + KHO + bo);
                ldm_x4(bl, sb + KLO + bo);
                mma_bf16(sacc[2 * nt], ah, bh);
                mma_bf16(sacc[2 * nt], ah, bl);
                mma_bf16(sacc[2 * nt], al, bh);
                mma_bf16(sacc[2 * nt + 1], ah, bh + 2);
                mma_bf16(sacc[2 * nt + 1], ah, bl + 2);
                mma_bf16(sacc[2 * nt + 1], al, bh + 2);
            }
        }

        // ---- ALiBi + window mask ----
#pragma unroll
        for (int t = 0; t < 8; t++) {
            int c0 = kt + t * 8 + ((lane & 3) << 1);
            int c1 = c0 + 1;
            int d00 = qr0 - c0, d01 = qr0 - c1, d10 = qr1 - c0, d11 = qr1 - c1;
            sacc[t][0] = (d00 >= 0 && d00 <= WINDOW) ? sacc[t][0] + slope2 * (float)d00 : -1e30f;
            sacc[t][1] = (d01 >= 0 && d01 <= WINDOW) ? sacc[t][1] + slope2 * (float)d01 : -1e30f;
            sacc[t][2] = (d10 >= 0 && d10 <= WINDOW) ? sacc[t][2] + slope2 * (float)d10 : -1e30f;
            sacc[t][3] = (d11 >= 0 && d11 <= WINDOW) ? sacc[t][3] + slope2 * (float)d11 : -1e30f;
        }

        // ---- online softmax (rows qr0, qr1) ----
        float mx0 = -1e30f, mx1 = -1e30f;
#pragma unroll
        for (int t = 0; t < 8; t++) {
            mx0 = fmaxf(mx0, fmaxf(sacc[t][0], sacc[t][1]));
            mx1 = fmaxf(mx1, fmaxf(sacc[t][2], sacc[t][3]));
        }
        mx0 = fmaxf(mx0, __shfl_xor_sync(0xffffffffu, mx0, 1));
        mx0 = fmaxf(mx0, __shfl_xor_sync(0xffffffffu, mx0, 2));
        mx1 = fmaxf(mx1, __shfl_xor_sync(0xffffffffu, mx1, 1));
        mx1 = fmaxf(mx1, __shfl_xor_sync(0xffffffffu, mx1, 2));
        float mn0 = fmaxf(m0r, mx0), mn1 = fmaxf(m1r, mx1);
        float a0 = exp2f(m0r - mn0), a1 = exp2f(m1r - mn1);
        m0r = mn0; m1r = mn1;

        float ps0 = 0.0f, ps1 = 0.0f;
#pragma unroll
        for (int t = 0; t < 8; t++) {
            sacc[t][0] = exp2f(sacc[t][0] - mn0);
            sacc[t][1] = exp2f(sacc[t][1] - mn0);
            sacc[t][2] = exp2f(sacc[t][2] - mn1);
            sacc[t][3] = exp2f(sacc[t][3] - mn1);
            ps0 += sacc[t][0] + sacc[t][1];
            ps1 += sacc[t][2] + sacc[t][3];
        }
        l0 = l0 * a0 + ps0;
        l1 = l1 * a1 + ps1;
#pragma unroll
        for (int t = 0; t < 16; t++) {
            oacc[t][0] *= a0; oacc[t][1] *= a0;
            oacc[t][2] *= a1; oacc[t][3] *= a1;
        }

        // ---- O += P V (3-term split), P frags straight from accumulators ----
#pragma unroll
        for (int kp = 0; kp < 4; kp++) {
            const float* s0 = sacc[2 * kp];
            const float* s1 = sacc[2 * kp + 1];
            uint32_t aPh[4], aPl[4];
            aPh[0] = __byte_perm(__float_as_uint(s0[0]), __float_as_uint(s0[1]), 0x7632);
            aPh[1] = __byte_perm(__float_as_uint(s0[2]), __float_as_uint(s0[3]), 0x7632);
            aPh[2] = __byte_perm(__float_as_uint(s1[0]), __float_as_uint(s1[1]), 0x7632);
            aPh[3] = __byte_perm(__float_as_uint(s1[2]), __float_as_uint(s1[3]), 0x7632);
            aPl[0] = pkbf(s0[0] - btrunc(s0[0]), s0[1] - btrunc(s0[1]));
            aPl[1] = pkbf(s0[2] - btrunc(s0[2]), s0[3] - btrunc(s0[3]));
            aPl[2] = pkbf(s1[0] - btrunc(s1[0]), s1[1] - btrunc(s1[1]));
            aPl[3] = pkbf(s1[2] - btrunc(s1[2]), s1[3] - btrunc(s1[3]));

            uint32_t vbase = voff_r + (uint32_t)(kp * 16) * TSTR_B;
#pragma unroll
            for (int nv = 0; nv < 8; nv++) {
                uint32_t bvh[4], bvl[4];
                uint32_t vo = vbase + nv * 32;
                ldm_x4t(bvh, sb + VHO + vo);
                ldm_x4t(bvl, sb + VLO + vo);
                mma_bf16(oacc[2 * nv], aPh, bvh);
                mma_bf16(oacc[2 * nv], aPh, bvl);
                mma_bf16(oacc[2 * nv], aPl, bvh);
                mma_bf16(oacc[2 * nv + 1], aPh, bvh + 2);
                mma_bf16(oacc[2 * nv + 1], aPh, bvl + 2);
                mma_bf16(oacc[2 * nv + 1], aPl, bvh + 2);
            }
        }
    }

    // ---- epilogue: reduce l over lane quad, normalize, store ----
    l0 += __shfl_xor_sync(0xffffffffu, l0, 1);
    l0 += __shfl_xor_sync(0xffffffffu, l0, 2);
    l1 += __shfl_xor_sync(0xffffffffu, l1, 1);
    l1 += __shfl_xor_sync(0xffffffffu, l1, 2);
    const float i0 = 1.0f / l0, i1 = 1.0f / l1;

    float* A0 = g_A + ((long)b * SEQ + qr0) * (QH * DIM) + h * DIM;
    float* A1 = g_A + ((long)b * SEQ + qr1) * (QH * DIM) + h * DIM;
#pragma unroll
    for (int t = 0; t < 16; t++) {
        int col = t * 8 + ((lane & 3) << 1);
        float2 v0 = make_float2(oacc[t][0] * i0, oacc[t][1] * i0);
        float2 v1 = make_float2(oacc[t][2] * i1, oacc[t][3] * i1);
        *(float2*)(A0 + col) = v0;
        *(float2*)(A1 + col) = v1;
    }
}

// ---------------------------------------------------------------------------
// Kernel C: out = g_A @ W_proj (fp32 SIMT)
// ---------------------------------------------------------------------------
__global__ void __launch_bounds__(256) proj_kernel(const float* __restrict__ Wp,
                                                   float* __restrict__ out) {
    __shared__ float As[32][66];
    __shared__ float Ws[64][130];
    const int m0 = blockIdx.x * 32;
    const int tid = threadIdx.x;
    const int ty = tid >> 4;
    const int tx = tid & 15;

    float acc[2][8] = {};

    for (int k0 = 0; k0 < 2048; k0 += 64) {
        for (int idx = tid; idx < 32 * 64; idx += 256) {
            int r = idx >> 6, c = idx & 63;
            As[r][c] = g_A[(long)(m0 + r) * 2048 + (k0 + c)];
        }
        for (int idx = tid; idx < 64 * 128; idx += 256) {
            int r = idx >> 7, c = idx & 127;
            Ws[r][c] = Wp[(k0 + r) * 128 + c];
        }
        __syncthreads();
#pragma unroll 8
        for (int k = 0; k < 64; k++) {
            float a[2], wv[8];
#pragma unroll
            for (int i = 0; i < 2; i++) a[i] = As[ty + 16 * i][k];
#pragma unroll
            for (int c = 0; c < 8; c++) wv[c] = Ws[k][tx + 16 * c];
#pragma unroll
            for (int i = 0; i < 2; i++)
#pragma unroll
                for (int c = 0; c < 8; c++) acc[i][c] += a[i] * wv[c];
        }
        __syncthreads();
    }

#pragma unroll
    for (int i = 0; i < 2; i++)
#pragma unroll
        for (int c = 0; c < 8; c++)
            out[(m0 + ty + 16 * i) * 128 + (tx + 16 * c)] = acc[i][c];
}

// ---------------------------------------------------------------------------
extern "C" void kernel_launch(void* const* d_in, const int* in_sizes, int n_in,
                              void* d_out, int out_size) {
    const float* x     = (const float*)d_in[0];
    const float* Wqkv  = (const float*)d_in[1];
    const float* Wproj = (const float*)d_in[2];
    float* out = (float*)d_out;

    qkv_kernel<<<dim3(8192 / 64, 3072 / 64), 256>>>(x, Wqkv);

    cudaFuncSetAttribute(attn_kernel, cudaFuncAttributeMaxDynamicSharedMemorySize, ATTN_SMEM);
    attn_kernel<<<dim3(SEQ / 64, QH, BATCH), 128, ATTN_SMEM>>>();

    proj_kernel<<<dim3(8192 / 32), 256>>>(Wproj, out);
}

// round 5
// speedup vs baseline: 3.0292x; 1.6753x over previous
#include <cuda_runtime.h>
#include <cuda_bf16.h>
#include <cstdint>
#include <math.h>

#define BATCH 4
#define SEQ 2048
#define DIM 128
#define QH 16
#define KVH 4
#define WINDOW 512

// ---------------------------------------------------------------------------
// device-global scratch (allocation-free)
// ---------------------------------------------------------------------------
__device__ __nv_bfloat16 g_Qh[BATCH * QH * SEQ * DIM];   // pre-scaled by log2e/sqrt(128)
__device__ __nv_bfloat16 g_Ql[BATCH * QH * SEQ * DIM];
__device__ __nv_bfloat16 g_Kh[BATCH * KVH * SEQ * DIM];
__device__ __nv_bfloat16 g_Kl[BATCH * KVH * SEQ * DIM];
__device__ __nv_bfloat16 g_Vh[BATCH * KVH * SEQ * DIM];
__device__ __nv_bfloat16 g_Vl[BATCH * KVH * SEQ * DIM];
__device__ float g_A[BATCH * SEQ * QH * DIM];            // [b][s][h*128+d]

// ---------------------------------------------------------------------------
// base-ISA helpers
// ---------------------------------------------------------------------------
__device__ __forceinline__ uint32_t smem_u32(const void* p) {
    uint32_t a;
    asm("{ .reg .u64 t; cvta.to.shared.u64 t, %1; cvt.u32.u64 %0, t; }" : "=r"(a) : "l"(p));
    return a;
}
__device__ __forceinline__ void ldm_x4(uint32_t* r, uint32_t addr) {
    asm volatile("ldmatrix.sync.aligned.m8n8.x4.shared.b16 {%0,%1,%2,%3},[%4];"
        : "=r"(r[0]), "=r"(r[1]), "=r"(r[2]), "=r"(r[3]) : "r"(addr));
}
__device__ __forceinline__ void ldm_x4t(uint32_t* r, uint32_t addr) {
    asm volatile("ldmatrix.sync.aligned.m8n8.x4.trans.shared.b16 {%0,%1,%2,%3},[%4];"
        : "=r"(r[0]), "=r"(r[1]), "=r"(r[2]), "=r"(r[3]) : "r"(addr));
}
__device__ __forceinline__ void mma_bf16(float* d, const uint32_t* a, const uint32_t* b) {
    asm volatile(
        "mma.sync.aligned.m16n8k16.row.col.f32.bf16.bf16.f32 "
        "{%0,%1,%2,%3},{%4,%5,%6,%7},{%8,%9},{%0,%1,%2,%3};"
        : "+f"(d[0]), "+f"(d[1]), "+f"(d[2]), "+f"(d[3])
        : "r"(a[0]), "r"(a[1]), "r"(a[2]), "r"(a[3]), "r"(b[0]), "r"(b[1]));
}
__device__ __forceinline__ uint32_t pkbf(float lo, float hi) {  // lo -> low half
    uint32_t r; asm("cvt.rn.bf16x2.f32 %0,%1,%2;" : "=r"(r) : "f"(hi), "f"(lo)); return r;
}
__device__ __forceinline__ float btrunc(float x) {
    return __uint_as_float(__float_as_uint(x) & 0xffff0000u);
}
__device__ __forceinline__ float ex2(float x) {   // single MUFU
    float y; asm("ex2.approx.ftz.f32 %0,%1;" : "=f"(y) : "f"(x)); return y;
}
__device__ __forceinline__ void cp16(uint32_t dst, const void* src) {
    asm volatile("cp.async.cg.shared.global [%0], [%1], 16;" :: "r"(dst), "l"(src));
}
__device__ __forceinline__ void cp_commit() { asm volatile("cp.async.commit_group;"); }
template <int N> __device__ __forceinline__ void cp_wait() {
    asm volatile("cp.async.wait_group %0;" :: "n"(N));
}

// ---------------------------------------------------------------------------
// Kernel A: qkv GEMM (fp32 SIMT) -> split-bf16 scatter (vectorized epilogue)
// cols per thread: d = 2*tx + 32*p + e  (p<2, e<2)
// ---------------------------------------------------------------------------
__global__ void __launch_bounds__(256) qkv_kernel(const float* __restrict__ x,
                                                  const float* __restrict__ Wqkv) {
    __shared__ float Xs[64][66];
    __shared__ float Ws[64][66];
    const int m0 = blockIdx.x * 64;
    const int n0 = blockIdx.y * 64;
    const int tid = threadIdx.x;
    const int ty = tid >> 4;
    const int tx = tid & 15;

    float acc[4][4] = {};   // [i][2p+e]

    for (int k0 = 0; k0 < 128; k0 += 64) {
        for (int idx = tid; idx < 64 * 64; idx += 256) {
            int r = idx >> 6, c = idx & 63;
            Xs[r][c] = x[(m0 + r) * 128 + (k0 + c)];
        }
        for (int idx = tid; idx < 64 * 64; idx += 256) {
            int r = idx >> 6, c = idx & 63;
            Ws[r][c] = Wqkv[(k0 + r) * 3072 + (n0 + c)];
        }
        __syncthreads();
#pragma unroll 8
        for (int k = 0; k < 64; k++) {
            float a[4];
            float2 wv[2];
#pragma unroll
            for (int i = 0; i < 4; i++) a[i] = Xs[ty + 16 * i][k];
#pragma unroll
            for (int p = 0; p < 2; p++) wv[p] = *(const float2*)&Ws[k][2 * tx + 32 * p];
#pragma unroll
            for (int i = 0; i < 4; i++) {
                acc[i][0] += a[i] * wv[0].x;
                acc[i][1] += a[i] * wv[0].y;
                acc[i][2] += a[i] * wv[1].x;
                acc[i][3] += a[i] * wv[1].y;
            }
        }
        __syncthreads();
    }

    const float qscale = 1.4426950408889634f * 0.08838834764831845f; // log2e/sqrt(128)
    const int head = n0 >> 7;
    const int dbase = n0 & 127;

    __nv_bfloat16 *dh, *dl;
    long hb;
    float sc = 1.0f;
    if (head < QH) {
        dh = g_Qh; dl = g_Ql; sc = qscale;
        hb = (long)head * SEQ;          // within [b]: (head*SEQ + s)*DIM (b applied below)
    } else if (head < QH + KVH) {
        dh = g_Kh; dl = g_Kl;
        hb = (long)(head - QH) * SEQ;
    } else {
        dh = g_Vh; dl = g_Vl;
        hb = (long)(head - QH - KVH) * SEQ;
    }
    const int nheads = (head < QH) ? QH : KVH;

#pragma unroll
    for (int i = 0; i < 4; i++) {
        int m = m0 + ty + 16 * i;
        int b = m >> 11, s = m & 2047;
        long rowo = ((long)b * nheads * SEQ + hb + s) * DIM + dbase + 2 * tx;
#pragma unroll
        for (int p = 0; p < 2; p++) {
            float v0 = acc[i][2 * p] * sc, v1 = acc[i][2 * p + 1] * sc;
            uint32_t hp = pkbf(v0, v1);
            float h0 = __uint_as_float(hp << 16);
            float h1 = __uint_as_float(hp & 0xffff0000u);
            uint32_t lp = pkbf(v0 - h0, v1 - h1);
            *(uint32_t*)(dh + rowo + 32 * p) = hp;
            *(uint32_t*)(dl + rowo + 32 * p) = lp;
        }
    }
}

// ---------------------------------------------------------------------------
// Kernel B: flash attention, HMMA split-bf16, 128-row q-tiles, cp.async
// double-buffered K/V. 256 threads (8 warps x 16 rows).
// ---------------------------------------------------------------------------
#define TSTR_B 272                    // 128 bf16 + 8 pad (16B aligned)
#define Q_BYTES (128 * TSTR_B)        // 34816
#define KV_TILE_B (64 * TSTR_B)       // 17408
#define STAGE_B (4 * KV_TILE_B)       // 69632
#define ST_OFF (2 * Q_BYTES)          // 69632
#define ATTN_SMEM (ST_OFF + 2 * STAGE_B)  // 208896

__global__ void __launch_bounds__(256) attn_kernel() {
    extern __shared__ char smc[];
    const uint32_t sb = smem_u32(smc);
    const int tid = threadIdx.x;
    const int lane = tid & 31;
    const int w = tid >> 5;
    const int m0w = w * 16;

    const int qt = blockIdx.x;
    const int h  = blockIdx.y;
    const int b  = blockIdx.z;
    const int g  = h >> 2;
    const int q0 = qt * 128;
    const float slope2 = exp2f(-(float)(h + 1) * 0.5f) * 1.4426950408889634f;

    const __nv_bfloat16* Qhg = g_Qh + ((long)(b * QH + h) * SEQ + q0) * DIM;
    const __nv_bfloat16* Qlg = g_Ql + ((long)(b * QH + h) * SEQ + q0) * DIM;
    const __nv_bfloat16* Khg = g_Kh + (long)(b * KVH + g) * SEQ * DIM;
    const __nv_bfloat16* Klg = g_Kl + (long)(b * KVH + g) * SEQ * DIM;
    const __nv_bfloat16* Vhg = g_Vh + (long)(b * KVH + g) * SEQ * DIM;
    const __nv_bfloat16* Vlg = g_Vl + (long)(b * KVH + g) * SEQ * DIM;

    const int ktlo = (q0 >= WINDOW) ? (q0 - WINDOW) : 0;
    const int nt = (q0 + 128 - ktlo) >> 6;

    // ---- prologue: Q (hi/lo) + KV stage 0 via cp.async, one group ----
    for (int idx = tid; idx < 4096; idx += 256) {
        int arr = idx >> 11, r = (idx >> 4) & 127, c = idx & 15;
        const char* src = (const char*)(arr ? Qlg : Qhg) + r * 256 + c * 16;
        cp16(sb + arr * Q_BYTES + r * TSTR_B + c * 16, src);
    }
    {
        const __nv_bfloat16* srcs[4] = { Khg, Klg, Vhg, Vlg };
        for (int idx = tid; idx < 4096; idx += 256) {
            int arr = idx >> 10, r = (idx >> 4) & 63, c = idx & 15;
            cp16(sb + ST_OFF + arr * KV_TILE_B + r * TSTR_B + c * 16,
                 (const char*)srcs[arr] + (long)(ktlo + r) * 256 + c * 16);
        }
    }
    cp_commit();

    float m0r = -1e30f, m1r = -1e30f, l0 = 0.0f, l1 = 0.0f;
    float oacc[16][4];
#pragma unroll
    for (int t = 0; t < 16; t++)
#pragma unroll
        for (int j = 0; j < 4; j++) oacc[t][j] = 0.0f;

    const int qr0 = q0 + m0w + (lane >> 2);
    const int qr1 = qr0 + 8;

    const uint32_t aoff = (uint32_t)(m0w + (lane & 15)) * TSTR_B + ((lane >> 4) << 3) * 2;
    const uint32_t boff_n = (uint32_t)(((lane >> 4) << 3) + (lane & 7)) * TSTR_B + (lane & 8) * 2;
    const uint32_t voff_r = (uint32_t)((lane & 8) + (lane & 7)) * TSTR_B + ((lane >> 4) << 3) * 2;

    for (int it = 0; it < nt; it++) {
        const int kt = ktlo + it * 64;
        const int st = it & 1;

        if (it + 1 < nt) {
            const int ktn = kt + 64;
            const uint32_t dstb = sb + ST_OFF + (st ^ 1) * STAGE_B;
            const __nv_bfloat16* srcs[4] = { Khg, Klg, Vhg, Vlg };
            for (int idx = tid; idx < 4096; idx += 256) {
                int arr = idx >> 10, r = (idx >> 4) & 63, c = idx & 15;
                cp16(dstb + arr * KV_TILE_B + r * TSTR_B + c * 16,
                     (const char*)srcs[arr] + (long)(ktn + r) * 256 + c * 16);
            }
            cp_commit();
            cp_wait<1>();
        } else {
            cp_wait<0>();
        }
        __syncthreads();

        const uint32_t kb = sb + ST_OFF + st * STAGE_B;
        const uint32_t KHO = kb, KLO = kb + KV_TILE_B;
        const uint32_t VHO = kb + 2 * KV_TILE_B, VLO = kb + 3 * KV_TILE_B;

        // ---- S = Q K^T (3-term split) ----
        float sacc[8][4];
#pragma unroll
        for (int t = 0; t < 8; t++)
#pragma unroll
            for (int j = 0; j < 4; j++) sacc[t][j] = 0.0f;

#pragma unroll
        for (int ks = 0; ks < 8; ks++) {
            uint32_t ah[4], al[4];
            ldm_x4(ah, sb + aoff + ks * 32);
            ldm_x4(al, sb + Q_BYTES + aoff + ks * 32);
#pragma unroll
            for (int ntl = 0; ntl < 4; ntl++) {
                uint32_t bh[4], bl[4];
                uint32_t bo = boff_n + (uint32_t)(ntl * 16) * TSTR_B + ks * 32;
                ldm_x4(bh, KHO + bo);
                ldm_x4(bl, KLO + bo);
                mma_bf16(sacc[2 * ntl], ah, bh);
                mma_bf16(sacc[2 * ntl], ah, bl);
                mma_bf16(sacc[2 * ntl], al, bh);
                mma_bf16(sacc[2 * ntl + 1], ah, bh + 2);
                mma_bf16(sacc[2 * ntl + 1], ah, bl + 2);
                mma_bf16(sacc[2 * ntl + 1], al, bh + 2);
            }
        }

        // ---- ALiBi + window mask (sentinel -1e32 < m_init) ----
#pragma unroll
        for (int t = 0; t < 8; t++) {
            int c0 = kt + t * 8 + ((lane & 3) << 1);
            int c1 = c0 + 1;
            int d00 = qr0 - c0, d01 = qr0 - c1, d10 = qr1 - c0, d11 = qr1 - c1;
            sacc[t][0] = (d00 >= 0 && d00 <= WINDOW) ? sacc[t][0] + slope2 * (float)d00 : -1e32f;
            sacc[t][1] = (d01 >= 0 && d01 <= WINDOW) ? sacc[t][1] + slope2 * (float)d01 : -1e32f;
            sacc[t][2] = (d10 >= 0 && d10 <= WINDOW) ? sacc[t][2] + slope2 * (float)d10 : -1e32f;
            sacc[t][3] = (d11 >= 0 && d11 <= WINDOW) ? sacc[t][3] + slope2 * (float)d11 : -1e32f;
        }

        // ---- online softmax ----
        float mx0 = -1e32f, mx1 = -1e32f;
#pragma unroll
        for (int t = 0; t < 8; t++) {
            mx0 = fmaxf(mx0, fmaxf(sacc[t][0], sacc[t][1]));
            mx1 = fmaxf(mx1, fmaxf(sacc[t][2], sacc[t][3]));
        }
        mx0 = fmaxf(mx0, __shfl_xor_sync(0xffffffffu, mx0, 1));
        mx0 = fmaxf(mx0, __shfl_xor_sync(0xffffffffu, mx0, 2));
        mx1 = fmaxf(mx1, __shfl_xor_sync(0xffffffffu, mx1, 1));
        mx1 = fmaxf(mx1, __shfl_xor_sync(0xffffffffu, mx1, 2));
        float mn0 = fmaxf(m0r, mx0), mn1 = fmaxf(m1r, mx1);
        float a0 = ex2(m0r - mn0), a1 = ex2(m1r - mn1);
        m0r = mn0; m1r = mn1;

        float ps0 = 0.0f, ps1 = 0.0f;
#pragma unroll
        for (int t = 0; t < 8; t++) {
            sacc[t][0] = ex2(sacc[t][0] - mn0);
            sacc[t][1] = ex2(sacc[t][1] - mn0);
            sacc[t][2] = ex2(sacc[t][2] - mn1);
            sacc[t][3] = ex2(sacc[t][3] - mn1);
            ps0 += sacc[t][0] + sacc[t][1];
            ps1 += sacc[t][2] + sacc[t][3];
        }
        l0 = l0 * a0 + ps0;
        l1 = l1 * a1 + ps1;
#pragma unroll
        for (int t = 0; t < 16; t++) {
            oacc[t][0] *= a0; oacc[t][1] *= a0;
            oacc[t][2] *= a1; oacc[t][3] *= a1;
        }

        // ---- O += P V (3-term split) ----
#pragma unroll
        for (int kp = 0; kp < 4; kp++) {
            const float* s0 = sacc[2 * kp];
            const float* s1 = sacc[2 * kp + 1];
            uint32_t aPh[4], aPl[4];
            aPh[0] = __byte_perm(__float_as_uint(s0[0]), __float_as_uint(s0[1]), 0x7632);
            aPh[1] = __byte_perm(__float_as_uint(s0[2]), __float_as_uint(s0[3]), 0x7632);
            aPh[2] = __byte_perm(__float_as_uint(s1[0]), __float_as_uint(s1[1]), 0x7632);
            aPh[3] = __byte_perm(__float_as_uint(s1[2]), __float_as_uint(s1[3]), 0x7632);
            aPl[0] = pkbf(s0[0] - btrunc(s0[0]), s0[1] - btrunc(s0[1]));
            aPl[1] = pkbf(s0[2] - btrunc(s0[2]), s0[3] - btrunc(s0[3]));
            aPl[2] = pkbf(s1[0] - btrunc(s1[0]), s1[1] - btrunc(s1[1]));
            aPl[3] = pkbf(s1[2] - btrunc(s1[2]), s1[3] - btrunc(s1[3]));

            uint32_t vbase = voff_r + (uint32_t)(kp * 16) * TSTR_B;
#pragma unroll
            for (int nv = 0; nv < 8; nv++) {
                uint32_t bvh[4], bvl[4];
                uint32_t vo = vbase + nv * 32;
                ldm_x4t(bvh, VHO + vo);
                ldm_x4t(bvl, VLO + vo);
                mma_bf16(oacc[2 * nv], aPh, bvh);
                mma_bf16(oacc[2 * nv], aPh, bvl);
                mma_bf16(oacc[2 * nv], aPl, bvh);
                mma_bf16(oacc[2 * nv + 1], aPh, bvh + 2);
                mma_bf16(oacc[2 * nv + 1], aPh, bvl + 2);
                mma_bf16(oacc[2 * nv + 1], aPl, bvh + 2);
            }
        }
        __syncthreads();
    }

    // ---- epilogue ----
    l0 += __shfl_xor_sync(0xffffffffu, l0, 1);
    l0 += __shfl_xor_sync(0xffffffffu, l0, 2);
    l1 += __shfl_xor_sync(0xffffffffu, l1, 1);
    l1 += __shfl_xor_sync(0xffffffffu, l1, 2);
    const float i0 = 1.0f / l0, i1 = 1.0f / l1;

    float* A0 = g_A + ((long)b * SEQ + qr0) * (QH * DIM) + h * DIM;
    float* A1 = g_A + ((long)b * SEQ + qr1) * (QH * DIM) + h * DIM;
#pragma unroll
    for (int t = 0; t < 16; t++) {
        int col = t * 8 + ((lane & 3) << 1);
        *(float2*)(A0 + col) = make_float2(oacc[t][0] * i0, oacc[t][1] * i0);
        *(float2*)(A1 + col) = make_float2(oacc[t][2] * i1, oacc[t][3] * i1);
    }
}

// ---------------------------------------------------------------------------
// Kernel C: out = g_A @ W_proj (fp32 SIMT)
// ---------------------------------------------------------------------------
__global__ void __launch_bounds__(256) proj_kernel(const float* __restrict__ Wp,
                                                   float* __restrict__ out) {
    __shared__ float As[32][66];
    __shared__ float Ws[64][130];
    const int m0 = blockIdx.x * 32;
    const int tid = threadIdx.x;
    const int ty = tid >> 4;
    const int tx = tid & 15;

    float acc[2][8] = {};

    for (int k0 = 0; k0 < 2048; k0 += 64) {
        for (int idx = tid; idx < 32 * 64; idx += 256) {
            int r = idx >> 6, c = idx & 63;
            As[r][c] = g_A[(long)(m0 + r) * 2048 + (k0 + c)];
        }
        for (int idx = tid; idx < 64 * 128; idx += 256) {
            int r = idx >> 7, c = idx & 127;
            Ws[r][c] = Wp[(k0 + r) * 128 + c];
        }
        __syncthreads();
#pragma unroll 8
        for (int k = 0; k < 64; k++) {
            float a[2], wv[8];
#pragma unroll
            for (int i = 0; i < 2; i++) a[i] = As[ty + 16 * i][k];
#pragma unroll
            for (int c = 0; c < 8; c++) wv[c] = Ws[k][tx + 16 * c];
#pragma unroll
            for (int i = 0; i < 2; i++)
#pragma unroll
                for (int c = 0; c < 8; c++) acc[i][c] += a[i] * wv[c];
        }
        __syncthreads();
    }

#pragma unroll
    for (int i = 0; i < 2; i++)
#pragma unroll
        for (int c = 0; c < 8; c++)
            out[(m0 + ty + 16 * i) * 128 + (tx + 16 * c)] = acc[i][c];
}

// ---------------------------------------------------------------------------
extern "C" void kernel_launch(void* const* d_in, const int* in_sizes, int n_in,
                              void* d_out, int out_size) {
    const float* x     = (const float*)d_in[0];
    const float* Wqkv  = (const float*)d_in[1];
    const float* Wproj = (const float*)d_in[2];
    float* out = (float*)d_out;

    qkv_kernel<<<dim3(8192 / 64, 3072 / 64), 256>>>(x, Wqkv);

    cudaFuncSetAttribute(attn_kernel, cudaFuncAttributeMaxDynamicSharedMemorySize, ATTN_SMEM);
    attn_kernel<<<dim3(SEQ / 128, QH, BATCH), 256, ATTN_SMEM>>>();

    proj_kernel<<<dim3(8192 / 32), 256>>>(Wproj, out);
}

// round 6
// speedup vs baseline: 4.3057x; 1.4214x over previous
#include <cuda_runtime.h>
#include <cuda_bf16.h>
#include <cstdint>
#include <math.h>

#define BATCH 4
#define SEQ 2048
#define DIM 128
#define QH 16
#define KVH 4
#define WINDOW 512

// ---------------------------------------------------------------------------
// device-global scratch (allocation-free)
// ---------------------------------------------------------------------------
__device__ __nv_bfloat16 g_Xh[BATCH * SEQ * DIM];        // split x
__device__ __nv_bfloat16 g_Xl[BATCH * SEQ * DIM];
__device__ __nv_bfloat16 g_Wqh[DIM * 3072];              // split W_qkv (Q cols pre-scaled)
__device__ __nv_bfloat16 g_Wql[DIM * 3072];
__device__ __nv_bfloat16 g_Wph[2048 * DIM];              // split W_proj
__device__ __nv_bfloat16 g_Wpl[2048 * DIM];
__device__ __nv_bfloat16 g_Qh[BATCH * QH * SEQ * DIM];
__device__ __nv_bfloat16 g_Ql[BATCH * QH * SEQ * DIM];
__device__ __nv_bfloat16 g_Kh[BATCH * KVH * SEQ * DIM];
__device__ __nv_bfloat16 g_Kl[BATCH * KVH * SEQ * DIM];
__device__ __nv_bfloat16 g_Vh[BATCH * KVH * SEQ * DIM];
__device__ __nv_bfloat16 g_Vl[BATCH * KVH * SEQ * DIM];
__device__ __nv_bfloat16 g_Ah[BATCH * SEQ * QH * DIM];   // split attention output
__device__ __nv_bfloat16 g_Al[BATCH * SEQ * QH * DIM];

// ---------------------------------------------------------------------------
// base-ISA helpers
// ---------------------------------------------------------------------------
__device__ __forceinline__ uint32_t smem_u32(const void* p) {
    uint32_t a;
    asm("{ .reg .u64 t; cvta.to.shared.u64 t, %1; cvt.u32.u64 %0, t; }" : "=r"(a) : "l"(p));
    return a;
}
__device__ __forceinline__ void ldm_x4(uint32_t* r, uint32_t addr) {
    asm volatile("ldmatrix.sync.aligned.m8n8.x4.shared.b16 {%0,%1,%2,%3},[%4];"
        : "=r"(r[0]), "=r"(r[1]), "=r"(r[2]), "=r"(r[3]) : "r"(addr));
}
__device__ __forceinline__ void ldm_x4t(uint32_t* r, uint32_t addr) {
    asm volatile("ldmatrix.sync.aligned.m8n8.x4.trans.shared.b16 {%0,%1,%2,%3},[%4];"
        : "=r"(r[0]), "=r"(r[1]), "=r"(r[2]), "=r"(r[3]) : "r"(addr));
}
__device__ __forceinline__ void mma_bf16(float* d, const uint32_t* a, const uint32_t* b) {
    asm volatile(
        "mma.sync.aligned.m16n8k16.row.col.f32.bf16.bf16.f32 "
        "{%0,%1,%2,%3},{%4,%5,%6,%7},{%8,%9},{%0,%1,%2,%3};"
        : "+f"(d[0]), "+f"(d[1]), "+f"(d[2]), "+f"(d[3])
        : "r"(a[0]), "r"(a[1]), "r"(a[2]), "r"(a[3]), "r"(b[0]), "r"(b[1]));
}
__device__ __forceinline__ uint32_t pkbf(float lo, float hi) {  // lo -> low half
    uint32_t r; asm("cvt.rn.bf16x2.f32 %0,%1,%2;" : "=r"(r) : "f"(hi), "f"(lo)); return r;
}
__device__ __forceinline__ float btrunc(float x) {
    return __uint_as_float(__float_as_uint(x) & 0xffff0000u);
}
__device__ __forceinline__ float ex2(float x) {
    float y; asm("ex2.approx.ftz.f32 %0,%1;" : "=f"(y) : "f"(x)); return y;
}
__device__ __forceinline__ void cp16(uint32_t dst, const void* src) {
    asm volatile("cp.async.cg.shared.global [%0], [%1], 16;" :: "r"(dst), "l"(src));
}
__device__ __forceinline__ void cp_commit() { asm volatile("cp.async.commit_group;"); }
template <int N> __device__ __forceinline__ void cp_wait() {
    asm volatile("cp.async.wait_group %0;" :: "n"(N));
}
// split one fp32 pair -> (hi u32, lo u32)
__device__ __forceinline__ void split2(float v0, float v1, uint32_t& hp, uint32_t& lp) {
    hp = pkbf(v0, v1);
    float h0 = __uint_as_float(hp << 16);
    float h1 = __uint_as_float(hp & 0xffff0000u);
    lp = pkbf(v0 - h0, v1 - h1);
}

// ---------------------------------------------------------------------------
// Kernel 0: split x / W_qkv / W_proj into bf16 hi/lo (Q cols of W_qkv scaled)
// one thread = 2 elements (u32 stores)
// ---------------------------------------------------------------------------
#define NPX (BATCH * SEQ * DIM / 2)      // 524288
#define NPQ (DIM * 3072 / 2)             // 196608
#define NPP (2048 * DIM / 2)             // 131072
__global__ void __launch_bounds__(256) prep_kernel(const float* __restrict__ x,
                                                   const float* __restrict__ Wqkv,
                                                   const float* __restrict__ Wproj) {
    const float qscale = 1.4426950408889634f * 0.08838834764831845f;
    int i = blockIdx.x * 256 + threadIdx.x;
    if (i < NPX) {
        float2 v = *(const float2*)(x + 2 * i);
        uint32_t hp, lp; split2(v.x, v.y, hp, lp);
        *(uint32_t*)(g_Xh + 2 * i) = hp; *(uint32_t*)(g_Xl + 2 * i) = lp;
    } else if (i < NPX + NPQ) {
        int j = i - NPX;
        float2 v = *(const float2*)(Wqkv + 2 * j);
        int col = (2 * j) % 3072;          // pair stays within one column parity group
        if (col < QH * DIM) { v.x *= qscale; v.y *= qscale; }
        uint32_t hp, lp; split2(v.x, v.y, hp, lp);
        *(uint32_t*)(g_Wqh + 2 * j) = hp; *(uint32_t*)(g_Wql + 2 * j) = lp;
    } else if (i < NPX + NPQ + NPP) {
        int j = i - NPX - NPQ;
        float2 v = *(const float2*)(Wproj + 2 * j);
        uint32_t hp, lp; split2(v.x, v.y, hp, lp);
        *(uint32_t*)(g_Wph + 2 * j) = hp; *(uint32_t*)(g_Wpl + 2 * j) = lp;
    }
}

// ---------------------------------------------------------------------------
// Kernel A: qkv = x @ W_qkv via HMMA split-bf16. Block 128m x 128n, K=128.
// 8 warps x 16 rows. head = blockIdx.y.
// ---------------------------------------------------------------------------
#define TSTR_B 272
#define QKV_TILE (128 * TSTR_B)          // 34816
#define QKV_SMEM (4 * QKV_TILE)          // 139264

__global__ void __launch_bounds__(256) qkv_kernel() {
    extern __shared__ char smc[];
    const uint32_t sb = smem_u32(smc);
    const int tid = threadIdx.x;
    const int lane = tid & 31;
    const int w = tid >> 5;
    const int m0w = w * 16;
    const int m0 = blockIdx.x * 128;
    const int head = blockIdx.y;         // 0..23
    const int n0 = head * 128;

    // cp.async: Xh, Xl (rows m0..m0+127, 128 bf16), Wh, Wl (k rows 0..127 of cols n0..n0+127)
    for (int idx = tid; idx < 8192; idx += 256) {
        int arr = idx >> 11, r = (idx >> 4) & 127, c = idx & 15;
        uint32_t dst = sb + arr * QKV_TILE + r * TSTR_B + c * 16;
        const char* src;
        if (arr == 0)      src = (const char*)g_Xh + (long)(m0 + r) * 256 + c * 16;
        else if (arr == 1) src = (const char*)g_Xl + (long)(m0 + r) * 256 + c * 16;
        else if (arr == 2) src = (const char*)g_Wqh + ((long)r * 3072 + n0) * 2 + c * 16;
        else               src = (const char*)g_Wql + ((long)r * 3072 + n0) * 2 + c * 16;
        cp16(dst, src);
    }
    cp_commit();
    cp_wait<0>();
    __syncthreads();

    const uint32_t XH = sb, XL = sb + QKV_TILE;
    const uint32_t WH = sb + 2 * QKV_TILE, WL = sb + 3 * QKV_TILE;
    const uint32_t aoff = (uint32_t)(m0w + (lane & 15)) * TSTR_B + ((lane >> 4) << 3) * 2;
    const uint32_t voff = (uint32_t)((lane & 8) + (lane & 7)) * TSTR_B + ((lane >> 4) << 3) * 2;

    float acc[16][4];
#pragma unroll
    for (int t = 0; t < 16; t++)
#pragma unroll
        for (int j = 0; j < 4; j++) acc[t][j] = 0.0f;

#pragma unroll
    for (int ks = 0; ks < 8; ks++) {
        uint32_t ah[4], al[4];
        ldm_x4(ah, XH + aoff + ks * 32);
        ldm_x4(al, XL + aoff + ks * 32);
        uint32_t vbase = voff + (uint32_t)(ks * 16) * TSTR_B;
#pragma unroll
        for (int nv = 0; nv < 8; nv++) {
            uint32_t bh[4], bl[4];
            ldm_x4t(bh, WH + vbase + nv * 32);
            ldm_x4t(bl, WL + vbase + nv * 32);
            mma_bf16(acc[2 * nv], ah, bh);
            mma_bf16(acc[2 * nv], ah, bl);
            mma_bf16(acc[2 * nv], al, bh);
            mma_bf16(acc[2 * nv + 1], ah, bh + 2);
            mma_bf16(acc[2 * nv + 1], ah, bl + 2);
            mma_bf16(acc[2 * nv + 1], al, bh + 2);
        }
    }

    // epilogue: split scatter into Q/K/V hi/lo
    __nv_bfloat16 *dh, *dl;
    int hh, nheads;
    if (head < QH)            { dh = g_Qh; dl = g_Ql; hh = head;            nheads = QH; }
    else if (head < QH + KVH) { dh = g_Kh; dl = g_Kl; hh = head - QH;       nheads = KVH; }
    else                      { dh = g_Vh; dl = g_Vl; hh = head - QH - KVH; nheads = KVH; }

    const int mr0 = m0 + m0w + (lane >> 2);
#pragma unroll
    for (int half = 0; half < 2; half++) {
        int m = mr0 + half * 8;
        int b = m >> 11, s = m & 2047;
        long rowo = ((long)(b * nheads + hh) * SEQ + s) * DIM + ((lane & 3) << 1);
#pragma unroll
        for (int t = 0; t < 16; t++) {
            uint32_t hp, lp;
            split2(acc[t][2 * half], acc[t][2 * half + 1], hp, lp);
            *(uint32_t*)(dh + rowo + t * 8) = hp;
            *(uint32_t*)(dl + rowo + t * 8) = lp;
        }
    }
}

// ---------------------------------------------------------------------------
// Kernel B: flash attention (unchanged core), epilogue writes split-bf16 A
// ---------------------------------------------------------------------------
#define Q_BYTES (128 * TSTR_B)
#define KV_TILE_B (64 * TSTR_B)
#define STAGE_B (4 * KV_TILE_B)
#define ST_OFF (2 * Q_BYTES)
#define ATTN_SMEM (ST_OFF + 2 * STAGE_B)  // 208896

__global__ void __launch_bounds__(256) attn_kernel() {
    extern __shared__ char smc[];
    const uint32_t sb = smem_u32(smc);
    const int tid = threadIdx.x;
    const int lane = tid & 31;
    const int w = tid >> 5;
    const int m0w = w * 16;

    const int qt = blockIdx.x;
    const int h  = blockIdx.y;
    const int b  = blockIdx.z;
    const int g  = h >> 2;
    const int q0 = qt * 128;
    const float slope2 = exp2f(-(float)(h + 1) * 0.5f) * 1.4426950408889634f;

    const __nv_bfloat16* Qhg = g_Qh + ((long)(b * QH + h) * SEQ + q0) * DIM;
    const __nv_bfloat16* Qlg = g_Ql + ((long)(b * QH + h) * SEQ + q0) * DIM;
    const __nv_bfloat16* Khg = g_Kh + (long)(b * KVH + g) * SEQ * DIM;
    const __nv_bfloat16* Klg = g_Kl + (long)(b * KVH + g) * SEQ * DIM;
    const __nv_bfloat16* Vhg = g_Vh + (long)(b * KVH + g) * SEQ * DIM;
    const __nv_bfloat16* Vlg = g_Vl + (long)(b * KVH + g) * SEQ * DIM;

    const int ktlo = (q0 >= WINDOW) ? (q0 - WINDOW) : 0;
    const int nt = (q0 + 128 - ktlo) >> 6;

    for (int idx = tid; idx < 4096; idx += 256) {
        int arr = idx >> 11, r = (idx >> 4) & 127, c = idx & 15;
        const char* src = (const char*)(arr ? Qlg : Qhg) + r * 256 + c * 16;
        cp16(sb + arr * Q_BYTES + r * TSTR_B + c * 16, src);
    }
    {
        const __nv_bfloat16* srcs[4] = { Khg, Klg, Vhg, Vlg };
        for (int idx = tid; idx < 4096; idx += 256) {
            int arr = idx >> 10, r = (idx >> 4) & 63, c = idx & 15;
            cp16(sb + ST_OFF + arr * KV_TILE_B + r * TSTR_B + c * 16,
                 (const char*)srcs[arr] + (long)(ktlo + r) * 256 + c * 16);
        }
    }
    cp_commit();

    float m0r = -1e30f, m1r = -1e30f, l0 = 0.0f, l1 = 0.0f;
    float oacc[16][4];
#pragma unroll
    for (int t = 0; t < 16; t++)
#pragma unroll
        for (int j = 0; j < 4; j++) oacc[t][j] = 0.0f;

    const int qr0 = q0 + m0w + (lane >> 2);
    const int qr1 = qr0 + 8;

    const uint32_t aoff = (uint32_t)(m0w + (lane & 15)) * TSTR_B + ((lane >> 4) << 3) * 2;
    const uint32_t boff_n = (uint32_t)(((lane >> 4) << 3) + (lane & 7)) * TSTR_B + (lane & 8) * 2;
    const uint32_t voff_r = (uint32_t)((lane & 8) + (lane & 7)) * TSTR_B + ((lane >> 4) << 3) * 2;

    for (int it = 0; it < nt; it++) {
        const int kt = ktlo + it * 64;
        const int st = it & 1;

        if (it + 1 < nt) {
            const int ktn = kt + 64;
            const uint32_t dstb = sb + ST_OFF + (st ^ 1) * STAGE_B;
            const __nv_bfloat16* srcs[4] = { Khg, Klg, Vhg, Vlg };
            for (int idx = tid; idx < 4096; idx += 256) {
                int arr = idx >> 10, r = (idx >> 4) & 63, c = idx & 15;
                cp16(dstb + arr * KV_TILE_B + r * TSTR_B + c * 16,
                     (const char*)srcs[arr] + (long)(ktn + r) * 256 + c * 16);
            }
            cp_commit();
            cp_wait<1>();
        } else {
            cp_wait<0>();
        }
        __syncthreads();

        const uint32_t kb = sb + ST_OFF + st * STAGE_B;
        const uint32_t KHO = kb, KLO = kb + KV_TILE_B;
        const uint32_t VHO = kb + 2 * KV_TILE_B, VLO = kb + 3 * KV_TILE_B;

        float sacc[8][4];
#pragma unroll
        for (int t = 0; t < 8; t++)
#pragma unroll
            for (int j = 0; j < 4; j++) sacc[t][j] = 0.0f;

#pragma unroll
        for (int ks = 0; ks < 8; ks++) {
            uint32_t ah[4], al[4];
            ldm_x4(ah, sb + aoff + ks * 32);
            ldm_x4(al, sb + Q_BYTES + aoff + ks * 32);
#pragma unroll
            for (int ntl = 0; ntl < 4; ntl++) {
                uint32_t bh[4], bl[4];
                uint32_t bo = boff_n + (uint32_t)(ntl * 16) * TSTR_B + ks * 32;
                ldm_x4(bh, KHO + bo);
                ldm_x4(bl, KLO + bo);
                mma_bf16(sacc[2 * ntl], ah, bh);
                mma_bf16(sacc[2 * ntl], ah, bl);
                mma_bf16(sacc[2 * ntl], al, bh);
                mma_bf16(sacc[2 * ntl + 1], ah, bh + 2);
                mma_bf16(sacc[2 * ntl + 1], ah, bl + 2);
                mma_bf16(sacc[2 * ntl + 1], al, bh + 2);
            }
        }

#pragma unroll
        for (int t = 0; t < 8; t++) {
            int c0 = kt + t * 8 + ((lane & 3) << 1);
            int c1 = c0 + 1;
            int d00 = qr0 - c0, d01 = qr0 - c1, d10 = qr1 - c0, d11 = qr1 - c1;
            sacc[t][0] = (d00 >= 0 && d00 <= WINDOW) ? sacc[t][0] + slope2 * (float)d00 : -1e32f;
            sacc[t][1] = (d01 >= 0 && d01 <= WINDOW) ? sacc[t][1] + slope2 * (float)d01 : -1e32f;
            sacc[t][2] = (d10 >= 0 && d10 <= WINDOW) ? sacc[t][2] + slope2 * (float)d10 : -1e32f;
            sacc[t][3] = (d11 >= 0 && d11 <= WINDOW) ? sacc[t][3] + slope2 * (float)d11 : -1e32f;
        }

        float mx0 = -1e32f, mx1 = -1e32f;
#pragma unroll
        for (int t = 0; t < 8; t++) {
            mx0 = fmaxf(mx0, fmaxf(sacc[t][0], sacc[t][1]));
            mx1 = fmaxf(mx1, fmaxf(sacc[t][2], sacc[t][3]));
        }
        mx0 = fmaxf(mx0, __shfl_xor_sync(0xffffffffu, mx0, 1));
        mx0 = fmaxf(mx0, __shfl_xor_sync(0xffffffffu, mx0, 2));
        mx1 = fmaxf(mx1, __shfl_xor_sync(0xffffffffu, mx1, 1));
        mx1 = fmaxf(mx1, __shfl_xor_sync(0xffffffffu, mx1, 2));
        float mn0 = fmaxf(m0r, mx0), mn1 = fmaxf(m1r, mx1);
        float a0 = ex2(m0r - mn0), a1 = ex2(m1r - mn1);
        m0r = mn0; m1r = mn1;

        float ps0 = 0.0f, ps1 = 0.0f;
#pragma unroll
        for (int t = 0; t < 8; t++) {
            sacc[t][0] = ex2(sacc[t][0] - mn0);
            sacc[t][1] = ex2(sacc[t][1] - mn0);
            sacc[t][2] = ex2(sacc[t][2] - mn1);
            sacc[t][3] = ex2(sacc[t][3] - mn1);
            ps0 += sacc[t][0] + sacc[t][1];
            ps1 += sacc[t][2] + sacc[t][3];
        }
        l0 = l0 * a0 + ps0;
        l1 = l1 * a1 + ps1;
#pragma unroll
        for (int t = 0; t < 16; t++) {
            oacc[t][0] *= a0; oacc[t][1] *= a0;
            oacc[t][2] *= a1; oacc[t][3] *= a1;
        }

#pragma unroll
        for (int kp = 0; kp < 4; kp++) {
            const float* s0 = sacc[2 * kp];
            const float* s1 = sacc[2 * kp + 1];
            uint32_t aPh[4], aPl[4];
            aPh[0] = __byte_perm(__float_as_uint(s0[0]), __float_as_uint(s0[1]), 0x7632);
            aPh[1] = __byte_perm(__float_as_uint(s0[2]), __float_as_uint(s0[3]), 0x7632);
            aPh[2] = __byte_perm(__float_as_uint(s1[0]), __float_as_uint(s1[1]), 0x7632);
            aPh[3] = __byte_perm(__float_as_uint(s1[2]), __float_as_uint(s1[3]), 0x7632);
            aPl[0] = pkbf(s0[0] - btrunc(s0[0]), s0[1] - btrunc(s0[1]));
            aPl[1] = pkbf(s0[2] - btrunc(s0[2]), s0[3] - btrunc(s0[3]));
            aPl[2] = pkbf(s1[0] - btrunc(s1[0]), s1[1] - btrunc(s1[1]));
            aPl[3] = pkbf(s1[2] - btrunc(s1[2]), s1[3] - btrunc(s1[3]));

            uint32_t vbase = voff_r + (uint32_t)(kp * 16) * TSTR_B;
#pragma unroll
            for (int nv = 0; nv < 8; nv++) {
                uint32_t bvh[4], bvl[4];
                uint32_t vo = vbase + nv * 32;
                ldm_x4t(bvh, VHO + vo);
                ldm_x4t(bvl, VLO + vo);
                mma_bf16(oacc[2 * nv], aPh, bvh);
                mma_bf16(oacc[2 * nv], aPh, bvl);
                mma_bf16(oacc[2 * nv], aPl, bvh);
                mma_bf16(oacc[2 * nv + 1], aPh, bvh + 2);
                mma_bf16(oacc[2 * nv + 1], aPh, bvl + 2);
                mma_bf16(oacc[2 * nv + 1], aPl, bvh + 2);
            }
        }
        __syncthreads();
    }

    // epilogue -> split bf16 A
    l0 += __shfl_xor_sync(0xffffffffu, l0, 1);
    l0 += __shfl_xor_sync(0xffffffffu, l0, 2);
    l1 += __shfl_xor_sync(0xffffffffu, l1, 1);
    l1 += __shfl_xor_sync(0xffffffffu, l1, 2);
    const float i0 = 1.0f / l0, i1 = 1.0f / l1;

    long r0 = ((long)b * SEQ + qr0) * (QH * DIM) + h * DIM + ((lane & 3) << 1);
    long r1 = ((long)b * SEQ + qr1) * (QH * DIM) + h * DIM + ((lane & 3) << 1);
#pragma unroll
    for (int t = 0; t < 16; t++) {
        uint32_t hp, lp;
        split2(oacc[t][0] * i0, oacc[t][1] * i0, hp, lp);
        *(uint32_t*)(g_Ah + r0 + t * 8) = hp;
        *(uint32_t*)(g_Al + r0 + t * 8) = lp;
        split2(oacc[t][2] * i1, oacc[t][3] * i1, hp, lp);
        *(uint32_t*)(g_Ah + r1 + t * 8) = hp;
        *(uint32_t*)(g_Al + r1 + t * 8) = lp;
    }
}

// ---------------------------------------------------------------------------
// Kernel C: out = A @ W_proj via HMMA split-bf16. Block 64m x 128n,
// K=2048 in 32 chunks of 64, cp.async double-buffered. 4 warps.
// ---------------------------------------------------------------------------
#define ASTR_B 144                       // 64 bf16 + 8 pad
#define PA_TILE (64 * ASTR_B)            // 9216
#define PW_TILE (64 * TSTR_B)            // 17408
#define PSTAGE (2 * PA_TILE + 2 * PW_TILE)   // 53248
#define PROJ_SMEM (2 * PSTAGE)           // 106496

__global__ void __launch_bounds__(128) proj_kernel(float* __restrict__ out) {
    extern __shared__ char smc[];
    const uint32_t sb = smem_u32(smc);
    const int tid = threadIdx.x;
    const int lane = tid & 31;
    const int w = tid >> 5;
    const int m0w = w * 16;
    const int m0 = blockIdx.x * 64;

    auto load_chunk = [&](int k0, uint32_t stage) {
        for (int idx = tid; idx < 3072; idx += 128) {
            if (idx < 1024) {
                int arr = idx >> 9, r = (idx >> 3) & 63, c = idx & 7;
                const char* src = (const char*)(arr ? g_Al : g_Ah) +
                                  (long)(m0 + r) * 4096 + k0 * 2 + c * 16;
                cp16(stage + arr * PA_TILE + r * ASTR_B + c * 16, src);
            } else {
                int j = idx - 1024;
                int arr = j >> 10, r = (j >> 4) & 63, c = j & 15;
                const char* src = (const char*)(arr ? g_Wpl : g_Wph) +
                                  (long)(k0 + r) * 256 + c * 16;
                cp16(stage + 2 * PA_TILE + arr * PW_TILE + r * TSTR_B + c * 16, src);
            }
        }
    };

    load_chunk(0, sb);
    cp_commit();

    const uint32_t aoffA = (uint32_t)(m0w + (lane & 15)) * ASTR_B + ((lane >> 4) << 3) * 2;
    const uint32_t voffW = (uint32_t)((lane & 8) + (lane & 7)) * TSTR_B + ((lane >> 4) << 3) * 2;

    float acc[16][4];
#pragma unroll
    for (int t = 0; t < 16; t++)
#pragma unroll
        for (int j = 0; j < 4; j++) acc[t][j] = 0.0f;

    for (int it = 0; it < 32; it++) {
        const int st = it & 1;
        if (it + 1 < 32) {
            load_chunk((it + 1) * 64, sb + (st ^ 1) * PSTAGE);
            cp_commit();
            cp_wait<1>();
        } else {
            cp_wait<0>();
        }
        __syncthreads();

        const uint32_t AH = sb + st * PSTAGE, AL = AH + PA_TILE;
        const uint32_t WH = AH + 2 * PA_TILE, WL = WH + PW_TILE;

#pragma unroll
        for (int ks = 0; ks < 4; ks++) {
            uint32_t ah[4], al[4];
            ldm_x4(ah, AH + aoffA + ks * 32);
            ldm_x4(al, AL + aoffA + ks * 32);
            uint32_t vbase = voffW + (uint32_t)(ks * 16) * TSTR_B;
#pragma unroll
            for (int nv = 0; nv < 8; nv++) {
                uint32_t bh[4], bl[4];
                ldm_x4t(bh, WH + vbase + nv * 32);
                ldm_x4t(bl, WL + vbase + nv * 32);
                mma_bf16(acc[2 * nv], ah, bh);
                mma_bf16(acc[2 * nv], ah, bl);
                mma_bf16(acc[2 * nv], al, bh);
                mma_bf16(acc[2 * nv + 1], ah, bh + 2);
                mma_bf16(acc[2 * nv + 1], ah, bl + 2);
                mma_bf16(acc[2 * nv + 1], al, bh + 2);
            }
        }
        __syncthreads();
    }

    const int mr0 = m0 + m0w + (lane >> 2);
#pragma unroll
    for (int t = 0; t < 16; t++) {
        int col = t * 8 + ((lane & 3) << 1);
        *(float2*)(out + (long)mr0 * 128 + col) = make_float2(acc[t][0], acc[t][1]);
        *(float2*)(out + (long)(mr0 + 8) * 128 + col) = make_float2(acc[t][2], acc[t][3]);
    }
}

// ---------------------------------------------------------------------------
extern "C" void kernel_launch(void* const* d_in, const int* in_sizes, int n_in,
                              void* d_out, int out_size) {
    const float* x     = (const float*)d_in[0];
    const float* Wqkv  = (const float*)d_in[1];
    const float* Wproj = (const float*)d_in[2];
    float* out = (float*)d_out;

    prep_kernel<<<(NPX + NPQ + NPP + 255) / 256, 256>>>(x, Wqkv, Wproj);

    cudaFuncSetAttribute(qkv_kernel, cudaFuncAttributeMaxDynamicSharedMemorySize, QKV_SMEM);
    qkv_kernel<<<dim3(8192 / 128, 24), 256, QKV_SMEM>>>();

    cudaFuncSetAttribute(attn_kernel, cudaFuncAttributeMaxDynamicSharedMemorySize, ATTN_SMEM);
    attn_kernel<<<dim3(SEQ / 128, QH, BATCH), 256, ATTN_SMEM>>>();

    cudaFuncSetAttribute(proj_kernel, cudaFuncAttributeMaxDynamicSharedMemorySize, PROJ_SMEM);
    proj_kernel<<<dim3(8192 / 64), 128, PROJ_SMEM>>>(out);
}

// round 7
// speedup vs baseline: 4.4704x; 1.0382x over previous
#include <cuda_runtime.h>
#include <cuda_bf16.h>
#include <cstdint>
#include <math.h>

#define BATCH 4
#define SEQ 2048
#define DIM 128
#define QH 16
#define KVH 4
#define WINDOW 512

// ---------------------------------------------------------------------------
// device-global scratch (allocation-free)
// ---------------------------------------------------------------------------
__device__ __nv_bfloat16 g_Xh[BATCH * SEQ * DIM];
__device__ __nv_bfloat16 g_Xl[BATCH * SEQ * DIM];
__device__ __nv_bfloat16 g_Wqh[DIM * 3072];
__device__ __nv_bfloat16 g_Wql[DIM * 3072];
__device__ __nv_bfloat16 g_Wph[2048 * DIM];
__device__ __nv_bfloat16 g_Wpl[2048 * DIM];
__device__ __nv_bfloat16 g_Qh[BATCH * QH * SEQ * DIM];
__device__ __nv_bfloat16 g_Ql[BATCH * QH * SEQ * DIM];
__device__ __nv_bfloat16 g_Kh[BATCH * KVH * SEQ * DIM];
__device__ __nv_bfloat16 g_Kl[BATCH * KVH * SEQ * DIM];
__device__ __nv_bfloat16 g_Vh[BATCH * KVH * SEQ * DIM];
__device__ __nv_bfloat16 g_Vl[BATCH * KVH * SEQ * DIM];
__device__ __nv_bfloat16 g_Ah[BATCH * SEQ * QH * DIM];
__device__ __nv_bfloat16 g_Al[BATCH * SEQ * QH * DIM];
__device__ float g_Pp[4 * BATCH * SEQ * DIM];            // proj split-K partials (16MB)

// ---------------------------------------------------------------------------
// base-ISA helpers
// ---------------------------------------------------------------------------
__device__ __forceinline__ uint32_t smem_u32(const void* p) {
    uint32_t a;
    asm("{ .reg .u64 t; cvta.to.shared.u64 t, %1; cvt.u32.u64 %0, t; }" : "=r"(a) : "l"(p));
    return a;
}
__device__ __forceinline__ void ldm_x4(uint32_t* r, uint32_t addr) {
    asm volatile("ldmatrix.sync.aligned.m8n8.x4.shared.b16 {%0,%1,%2,%3},[%4];"
        : "=r"(r[0]), "=r"(r[1]), "=r"(r[2]), "=r"(r[3]) : "r"(addr));
}
__device__ __forceinline__ void ldm_x4t(uint32_t* r, uint32_t addr) {
    asm volatile("ldmatrix.sync.aligned.m8n8.x4.trans.shared.b16 {%0,%1,%2,%3},[%4];"
        : "=r"(r[0]), "=r"(r[1]), "=r"(r[2]), "=r"(r[3]) : "r"(addr));
}
__device__ __forceinline__ void mma_bf16(float* d, const uint32_t* a, const uint32_t* b) {
    asm volatile(
        "mma.sync.aligned.m16n8k16.row.col.f32.bf16.bf16.f32 "
        "{%0,%1,%2,%3},{%4,%5,%6,%7},{%8,%9},{%0,%1,%2,%3};"
        : "+f"(d[0]), "+f"(d[1]), "+f"(d[2]), "+f"(d[3])
        : "r"(a[0]), "r"(a[1]), "r"(a[2]), "r"(a[3]), "r"(b[0]), "r"(b[1]));
}
__device__ __forceinline__ uint32_t pkbf(float lo, float hi) {
    uint32_t r; asm("cvt.rn.bf16x2.f32 %0,%1,%2;" : "=r"(r) : "f"(hi), "f"(lo)); return r;
}
__device__ __forceinline__ float btrunc(float x) {
    return __uint_as_float(__float_as_uint(x) & 0xffff0000u);
}
__device__ __forceinline__ float ex2(float x) {
    float y; asm("ex2.approx.ftz.f32 %0,%1;" : "=f"(y) : "f"(x)); return y;
}
__device__ __forceinline__ void cp16(uint32_t dst, const void* src) {
    asm volatile("cp.async.cg.shared.global [%0], [%1], 16;" :: "r"(dst), "l"(src));
}
__device__ __forceinline__ void cp_commit() { asm volatile("cp.async.commit_group;"); }
template <int N> __device__ __forceinline__ void cp_wait() {
    asm volatile("cp.async.wait_group %0;" :: "n"(N));
}
__device__ __forceinline__ void split2(float v0, float v1, uint32_t& hp, uint32_t& lp) {
    hp = pkbf(v0, v1);
    float h0 = __uint_as_float(hp << 16);
    float h1 = __uint_as_float(hp & 0xffff0000u);
    lp = pkbf(v0 - h0, v1 - h1);
}

// ---------------------------------------------------------------------------
// Kernel 0: split inputs into bf16 hi/lo
// ---------------------------------------------------------------------------
#define NPX (BATCH * SEQ * DIM / 2)
#define NPQ (DIM * 3072 / 2)
#define NPP (2048 * DIM / 2)
__global__ void __launch_bounds__(256) prep_kernel(const float* __restrict__ x,
                                                   const float* __restrict__ Wqkv,
                                                   const float* __restrict__ Wproj) {
    const float qscale = 1.4426950408889634f * 0.08838834764831845f;
    int i = blockIdx.x * 256 + threadIdx.x;
    if (i < NPX) {
        float2 v = *(const float2*)(x + 2 * i);
        uint32_t hp, lp; split2(v.x, v.y, hp, lp);
        *(uint32_t*)(g_Xh + 2 * i) = hp; *(uint32_t*)(g_Xl + 2 * i) = lp;
    } else if (i < NPX + NPQ) {
        int j = i - NPX;
        float2 v = *(const float2*)(Wqkv + 2 * j);
        int col = (2 * j) % 3072;
        if (col < QH * DIM) { v.x *= qscale; v.y *= qscale; }
        uint32_t hp, lp; split2(v.x, v.y, hp, lp);
        *(uint32_t*)(g_Wqh + 2 * j) = hp; *(uint32_t*)(g_Wql + 2 * j) = lp;
    } else if (i < NPX + NPQ + NPP) {
        int j = i - NPX - NPQ;
        float2 v = *(const float2*)(Wproj + 2 * j);
        uint32_t hp, lp; split2(v.x, v.y, hp, lp);
        *(uint32_t*)(g_Wph + 2 * j) = hp; *(uint32_t*)(g_Wpl + 2 * j) = lp;
    }
}

// ---------------------------------------------------------------------------
// Kernel A: qkv via HMMA, 2-phase k-pipelined loads (k 0-63 then 64-127)
// ---------------------------------------------------------------------------
#define TSTR_B 272
#define QKV_TILE (128 * TSTR_B)
#define QKV_SMEM (4 * QKV_TILE)

__global__ void __launch_bounds__(256) qkv_kernel() {
    extern __shared__ char smc[];
    const uint32_t sb = smem_u32(smc);
    const int tid = threadIdx.x;
    const int lane = tid & 31;
    const int w = tid >> 5;
    const int m0w = w * 16;
    const int m0 = blockIdx.x * 128;
    const int head = blockIdx.y;
    const int n0 = head * 128;

    // phase 1: X cols 0-63 (chunks c<8), W k-rows 0-63
    for (int idx = tid; idx < 4096; idx += 256) {
        if (idx < 2048) {  // X: 2 arrays x 128 rows x 8 chunks
            int arr = idx >> 10, r = (idx >> 3) & 127, c = idx & 7;
            const char* src = (const char*)(arr ? g_Xl : g_Xh) + (long)(m0 + r) * 256 + c * 16;
            cp16(sb + arr * QKV_TILE + r * TSTR_B + c * 16, src);
        } else {           // W: 2 arrays x 64 rows x 16 chunks
            int j = idx - 2048;
            int arr = j >> 10, r = (j >> 4) & 63, c = j & 15;
            const char* src = (const char*)(arr ? g_Wql : g_Wqh) + ((long)r * 3072 + n0) * 2 + c * 16;
            cp16(sb + (2 + arr) * QKV_TILE + r * TSTR_B + c * 16, src);
        }
    }
    cp_commit();
    // phase 2: X cols 64-127, W k-rows 64-127
    for (int idx = tid; idx < 4096; idx += 256) {
        if (idx < 2048) {
            int arr = idx >> 10, r = (idx >> 3) & 127, c = (idx & 7) + 8;
            const char* src = (const char*)(arr ? g_Xl : g_Xh) + (long)(m0 + r) * 256 + c * 16;
            cp16(sb + arr * QKV_TILE + r * TSTR_B + c * 16, src);
        } else {
            int j = idx - 2048;
            int arr = j >> 10, r = ((j >> 4) & 63) + 64, c = j & 15;
            const char* src = (const char*)(arr ? g_Wql : g_Wqh) + ((long)r * 3072 + n0) * 2 + c * 16;
            cp16(sb + (2 + arr) * QKV_TILE + r * TSTR_B + c * 16, src);
        }
    }
    cp_commit();

    const uint32_t XH = sb, XL = sb + QKV_TILE;
    const uint32_t WH = sb + 2 * QKV_TILE, WL = sb + 3 * QKV_TILE;
    const uint32_t aoff = (uint32_t)(m0w + (lane & 15)) * TSTR_B + ((lane >> 4) << 3) * 2;
    const uint32_t voff = (uint32_t)((lane & 8) + (lane & 7)) * TSTR_B + ((lane >> 4) << 3) * 2;

    float acc[16][4];
#pragma unroll
    for (int t = 0; t < 16; t++)
#pragma unroll
        for (int j = 0; j < 4; j++) acc[t][j] = 0.0f;

#pragma unroll
    for (int ph = 0; ph < 2; ph++) {
        if (ph == 0) cp_wait<1>(); else cp_wait<0>();
        __syncthreads();
#pragma unroll
        for (int ks2 = 0; ks2 < 4; ks2++) {
            int ks = ph * 4 + ks2;
            uint32_t ah[4], al[4];
            ldm_x4(ah, XH + aoff + ks * 32);
            ldm_x4(al, XL + aoff + ks * 32);
            uint32_t vbase = voff + (uint32_t)(ks * 16) * TSTR_B;
#pragma unroll
            for (int nv = 0; nv < 8; nv++) {
                uint32_t bh[4], bl[4];
                ldm_x4t(bh, WH + vbase + nv * 32);
                ldm_x4t(bl, WL + vbase + nv * 32);
                mma_bf16(acc[2 * nv], ah, bh);
                mma_bf16(acc[2 * nv], ah, bl);
                mma_bf16(acc[2 * nv], al, bh);
                mma_bf16(acc[2 * nv + 1], ah, bh + 2);
                mma_bf16(acc[2 * nv + 1], ah, bl + 2);
                mma_bf16(acc[2 * nv + 1], al, bh + 2);
            }
        }
    }

    __nv_bfloat16 *dh, *dl;
    int hh, nheads;
    if (head < QH)            { dh = g_Qh; dl = g_Ql; hh = head;            nheads = QH; }
    else if (head < QH + KVH) { dh = g_Kh; dl = g_Kl; hh = head - QH;       nheads = KVH; }
    else                      { dh = g_Vh; dl = g_Vl; hh = head - QH - KVH; nheads = KVH; }

    const int mr0 = m0 + m0w + (lane >> 2);
#pragma unroll
    for (int half = 0; half < 2; half++) {
        int m = mr0 + half * 8;
        int b = m >> 11, s = m & 2047;
        long rowo = ((long)(b * nheads + hh) * SEQ + s) * DIM + ((lane & 3) << 1);
#pragma unroll
        for (int t = 0; t < 16; t++) {
            uint32_t hp, lp;
            split2(acc[t][2 * half], acc[t][2 * half + 1], hp, lp);
            *(uint32_t*)(dh + rowo + t * 8) = hp;
            *(uint32_t*)(dl + rowo + t * 8) = lp;
        }
    }
}

// ---------------------------------------------------------------------------
// Kernel B: flash attention (unchanged known-good core)
// ---------------------------------------------------------------------------
#define Q_BYTES (128 * TSTR_B)
#define KV_TILE_B (64 * TSTR_B)
#define STAGE_B (4 * KV_TILE_B)
#define ST_OFF (2 * Q_BYTES)
#define ATTN_SMEM (ST_OFF + 2 * STAGE_B)

__global__ void __launch_bounds__(256) attn_kernel() {
    extern __shared__ char smc[];
    const uint32_t sb = smem_u32(smc);
    const int tid = threadIdx.x;
    const int lane = tid & 31;
    const int w = tid >> 5;
    const int m0w = w * 16;

    const int qt = blockIdx.x;
    const int h  = blockIdx.y;
    const int b  = blockIdx.z;
    const int g  = h >> 2;
    const int q0 = qt * 128;
    const float slope2 = exp2f(-(float)(h + 1) * 0.5f) * 1.4426950408889634f;

    const __nv_bfloat16* Qhg = g_Qh + ((long)(b * QH + h) * SEQ + q0) * DIM;
    const __nv_bfloat16* Qlg = g_Ql + ((long)(b * QH + h) * SEQ + q0) * DIM;
    const __nv_bfloat16* Khg = g_Kh + (long)(b * KVH + g) * SEQ * DIM;
    const __nv_bfloat16* Klg = g_Kl + (long)(b * KVH + g) * SEQ * DIM;
    const __nv_bfloat16* Vhg = g_Vh + (long)(b * KVH + g) * SEQ * DIM;
    const __nv_bfloat16* Vlg = g_Vl + (long)(b * KVH + g) * SEQ * DIM;

    const int ktlo = (q0 >= WINDOW) ? (q0 - WINDOW) : 0;
    const int nt = (q0 + 128 - ktlo) >> 6;

    for (int idx = tid; idx < 4096; idx += 256) {
        int arr = idx >> 11, r = (idx >> 4) & 127, c = idx & 15;
        const char* src = (const char*)(arr ? Qlg : Qhg) + r * 256 + c * 16;
        cp16(sb + arr * Q_BYTES + r * TSTR_B + c * 16, src);
    }
    {
        const __nv_bfloat16* srcs[4] = { Khg, Klg, Vhg, Vlg };
        for (int idx = tid; idx < 4096; idx += 256) {
            int arr = idx >> 10, r = (idx >> 4) & 63, c = idx & 15;
            cp16(sb + ST_OFF + arr * KV_TILE_B + r * TSTR_B + c * 16,
                 (const char*)srcs[arr] + (long)(ktlo + r) * 256 + c * 16);
        }
    }
    cp_commit();

    float m0r = -1e30f, m1r = -1e30f, l0 = 0.0f, l1 = 0.0f;
    float oacc[16][4];
#pragma unroll
    for (int t = 0; t < 16; t++)
#pragma unroll
        for (int j = 0; j < 4; j++) oacc[t][j] = 0.0f;

    const int qr0 = q0 + m0w + (lane >> 2);
    const int qr1 = qr0 + 8;

    const uint32_t aoff = (uint32_t)(m0w + (lane & 15)) * TSTR_B + ((lane >> 4) << 3) * 2;
    const uint32_t boff_n = (uint32_t)(((lane >> 4) << 3) + (lane & 7)) * TSTR_B + (lane & 8) * 2;
    const uint32_t voff_r = (uint32_t)((lane & 8) + (lane & 7)) * TSTR_B + ((lane >> 4) << 3) * 2;

    for (int it = 0; it < nt; it++) {
        const int kt = ktlo + it * 64;
        const int st = it & 1;

        if (it + 1 < nt) {
            const int ktn = kt + 64;
            const uint32_t dstb = sb + ST_OFF + (st ^ 1) * STAGE_B;
            const __nv_bfloat16* srcs[4] = { Khg, Klg, Vhg, Vlg };
            for (int idx = tid; idx < 4096; idx += 256) {
                int arr = idx >> 10, r = (idx >> 4) & 63, c = idx & 15;
                cp16(dstb + arr * KV_TILE_B + r * TSTR_B + c * 16,
                     (const char*)srcs[arr] + (long)(ktn + r) * 256 + c * 16);
            }
            cp_commit();
            cp_wait<1>();
        } else {
            cp_wait<0>();
        }
        __syncthreads();

        const uint32_t kb = sb + ST_OFF + st * STAGE_B;
        const uint32_t KHO = kb, KLO = kb + KV_TILE_B;
        const uint32_t VHO = kb + 2 * KV_TILE_B, VLO = kb + 3 * KV_TILE_B;

        float sacc[8][4];
#pragma unroll
        for (int t = 0; t < 8; t++)
#pragma unroll
            for (int j = 0; j < 4; j++) sacc[t][j] = 0.0f;

#pragma unroll
        for (int ks = 0; ks < 8; ks++) {
            uint32_t ah[4], al[4];
            ldm_x4(ah, sb + aoff + ks * 32);
            ldm_x4(al, sb + Q_BYTES + aoff + ks * 32);
#pragma unroll
            for (int ntl = 0; ntl < 4; ntl++) {
                uint32_t bh[4], bl[4];
                uint32_t bo = boff_n + (uint32_t)(ntl * 16) * TSTR_B + ks * 32;
                ldm_x4(bh, KHO + bo);
                ldm_x4(bl, KLO + bo);
                mma_bf16(sacc[2 * ntl], ah, bh);
                mma_bf16(sacc[2 * ntl], ah, bl);
                mma_bf16(sacc[2 * ntl], al, bh);
                mma_bf16(sacc[2 * ntl + 1], ah, bh + 2);
                mma_bf16(sacc[2 * ntl + 1], ah, bl + 2);
                mma_bf16(sacc[2 * ntl + 1], al, bh + 2);
            }
        }

#pragma unroll
        for (int t = 0; t < 8; t++) {
            int c0 = kt + t * 8 + ((lane & 3) << 1);
            int c1 = c0 + 1;
            int d00 = qr0 - c0, d01 = qr0 - c1, d10 = qr1 - c0, d11 = qr1 - c1;
            sacc[t][0] = (d00 >= 0 && d00 <= WINDOW) ? sacc[t][0] + slope2 * (float)d00 : -1e32f;
            sacc[t][1] = (d01 >= 0 && d01 <= WINDOW) ? sacc[t][1] + slope2 * (float)d01 : -1e32f;
            sacc[t][2] = (d10 >= 0 && d10 <= WINDOW) ? sacc[t][2] + slope2 * (float)d10 : -1e32f;
            sacc[t][3] = (d11 >= 0 && d11 <= WINDOW) ? sacc[t][3] + slope2 * (float)d11 : -1e32f;
        }

        float mx0 = -1e32f, mx1 = -1e32f;
#pragma unroll
        for (int t = 0; t < 8; t++) {
            mx0 = fmaxf(mx0, fmaxf(sacc[t][0], sacc[t][1]));
            mx1 = fmaxf(mx1, fmaxf(sacc[t][2], sacc[t][3]));
        }
        mx0 = fmaxf(mx0, __shfl_xor_sync(0xffffffffu, mx0, 1));
        mx0 = fmaxf(mx0, __shfl_xor_sync(0xffffffffu, mx0, 2));
        mx1 = fmaxf(mx1, __shfl_xor_sync(0xffffffffu, mx1, 1));
        mx1 = fmaxf(mx1, __shfl_xor_sync(0xffffffffu, mx1, 2));
        float mn0 = fmaxf(m0r, mx0), mn1 = fmaxf(m1r, mx1);
        float a0 = ex2(m0r - mn0), a1 = ex2(m1r - mn1);
        m0r = mn0; m1r = mn1;

        float ps0 = 0.0f, ps1 = 0.0f;
#pragma unroll
        for (int t = 0; t < 8; t++) {
            sacc[t][0] = ex2(sacc[t][0] - mn0);
            sacc[t][1] = ex2(sacc[t][1] - mn0);
            sacc[t][2] = ex2(sacc[t][2] - mn1);
            sacc[t][3] = ex2(sacc[t][3] - mn1);
            ps0 += sacc[t][0] + sacc[t][1];
            ps1 += sacc[t][2] + sacc[t][3];
        }
        l0 = l0 * a0 + ps0;
        l1 = l1 * a1 + ps1;
#pragma unroll
        for (int t = 0; t < 16; t++) {
            oacc[t][0] *= a0; oacc[t][1] *= a0;
            oacc[t][2] *= a1; oacc[t][3] *= a1;
        }

#pragma unroll
        for (int kp = 0; kp < 4; kp++) {
            const float* s0 = sacc[2 * kp];
            const float* s1 = sacc[2 * kp + 1];
            uint32_t aPh[4], aPl[4];
            aPh[0] = __byte_perm(__float_as_uint(s0[0]), __float_as_uint(s0[1]), 0x7632);
            aPh[1] = __byte_perm(__float_as_uint(s0[2]), __float_as_uint(s0[3]), 0x7632);
            aPh[2] = __byte_perm(__float_as_uint(s1[0]), __float_as_uint(s1[1]), 0x7632);
            aPh[3] = __byte_perm(__float_as_uint(s1[2]), __float_as_uint(s1[3]), 0x7632);
            aPl[0] = pkbf(s0[0] - btrunc(s0[0]), s0[1] - btrunc(s0[1]));
            aPl[1] = pkbf(s0[2] - btrunc(s0[2]), s0[3] - btrunc(s0[3]));
            aPl[2] = pkbf(s1[0] - btrunc(s1[0]), s1[1] - btrunc(s1[1]));
            aPl[3] = pkbf(s1[2] - btrunc(s1[2]), s1[3] - btrunc(s1[3]));

            uint32_t vbase = voff_r + (uint32_t)(kp * 16) * TSTR_B;
#pragma unroll
            for (int nv = 0; nv < 8; nv++) {
                uint32_t bvh[4], bvl[4];
                uint32_t vo = vbase + nv * 32;
                ldm_x4t(bvh, VHO + vo);
                ldm_x4t(bvl, VLO + vo);
                mma_bf16(oacc[2 * nv], aPh, bvh);
                mma_bf16(oacc[2 * nv], aPh, bvl);
                mma_bf16(oacc[2 * nv], aPl, bvh);
                mma_bf16(oacc[2 * nv + 1], aPh, bvh + 2);
                mma_bf16(oacc[2 * nv + 1], aPh, bvl + 2);
                mma_bf16(oacc[2 * nv + 1], aPl, bvh + 2);
            }
        }
        __syncthreads();
    }

    l0 += __shfl_xor_sync(0xffffffffu, l0, 1);
    l0 += __shfl_xor_sync(0xffffffffu, l0, 2);
    l1 += __shfl_xor_sync(0xffffffffu, l1, 1);
    l1 += __shfl_xor_sync(0xffffffffu, l1, 2);
    const float i0 = 1.0f / l0, i1 = 1.0f / l1;

    long r0 = ((long)b * SEQ + qr0) * (QH * DIM) + h * DIM + ((lane & 3) << 1);
    long r1 = ((long)b * SEQ + qr1) * (QH * DIM) + h * DIM + ((lane & 3) << 1);
#pragma unroll
    for (int t = 0; t < 16; t++) {
        uint32_t hp, lp;
        split2(oacc[t][0] * i0, oacc[t][1] * i0, hp, lp);
        *(uint32_t*)(g_Ah + r0 + t * 8) = hp;
        *(uint32_t*)(g_Al + r0 + t * 8) = lp;
        split2(oacc[t][2] * i1, oacc[t][3] * i1, hp, lp);
        *(uint32_t*)(g_Ah + r1 + t * 8) = hp;
        *(uint32_t*)(g_Al + r1 + t * 8) = lp;
    }
}

// ---------------------------------------------------------------------------
// Kernel C: proj split-K partials. grid (128, 4); block 64m x 128n, K=512.
// ---------------------------------------------------------------------------
#define ASTR_B 144
#define PA_TILE (64 * ASTR_B)
#define PW_TILE (64 * TSTR_B)
#define PSTAGE (2 * PA_TILE + 2 * PW_TILE)
#define PROJ_SMEM (2 * PSTAGE)

__global__ void __launch_bounds__(128) proj_partial_kernel() {
    extern __shared__ char smc[];
    const uint32_t sb = smem_u32(smc);
    const int tid = threadIdx.x;
    const int lane = tid & 31;
    const int w = tid >> 5;
    const int m0w = w * 16;
    const int m0 = blockIdx.x * 64;
    const int ksplit = blockIdx.y;
    const int kbase = ksplit * 512;

    auto load_chunk = [&](int k0, uint32_t stage) {
        for (int idx = tid; idx < 3072; idx += 128) {
            if (idx < 1024) {
                int arr = idx >> 9, r = (idx >> 3) & 63, c = idx & 7;
                const char* src = (const char*)(arr ? g_Al : g_Ah) +
                                  (long)(m0 + r) * 4096 + k0 * 2 + c * 16;
                cp16(stage + arr * PA_TILE + r * ASTR_B + c * 16, src);
            } else {
                int j = idx - 1024;
                int arr = j >> 10, r = (j >> 4) & 63, c = j & 15;
                const char* src = (const char*)(arr ? g_Wpl : g_Wph) +
                                  (long)(k0 + r) * 256 + c * 16;
                cp16(stage + 2 * PA_TILE + arr * PW_TILE + r * TSTR_B + c * 16, src);
            }
        }
    };

    load_chunk(kbase, sb);
    cp_commit();

    const uint32_t aoffA = (uint32_t)(m0w + (lane & 15)) * ASTR_B + ((lane >> 4) << 3) * 2;
    const uint32_t voffW = (uint32_t)((lane & 8) + (lane & 7)) * TSTR_B + ((lane >> 4) << 3) * 2;

    float acc[16][4];
#pragma unroll
    for (int t = 0; t < 16; t++)
#pragma unroll
        for (int j = 0; j < 4; j++) acc[t][j] = 0.0f;

    for (int it = 0; it < 8; it++) {
        const int st = it & 1;
        if (it + 1 < 8) {
            load_chunk(kbase + (it + 1) * 64, sb + (st ^ 1) * PSTAGE);
            cp_commit();
            cp_wait<1>();
        } else {
            cp_wait<0>();
        }
        __syncthreads();

        const uint32_t AH = sb + st * PSTAGE, AL = AH + PA_TILE;
        const uint32_t WH = AH + 2 * PA_TILE, WL = WH + PW_TILE;

#pragma unroll
        for (int ks = 0; ks < 4; ks++) {
            uint32_t ah[4], al[4];
            ldm_x4(ah, AH + aoffA + ks * 32);
            ldm_x4(al, AL + aoffA + ks * 32);
            uint32_t vbase = voffW + (uint32_t)(ks * 16) * TSTR_B;
#pragma unroll
            for (int nv = 0; nv < 8; nv++) {
                uint32_t bh[4], bl[4];
                ldm_x4t(bh, WH + vbase + nv * 32);
                ldm_x4t(bl, WL + vbase + nv * 32);
                mma_bf16(acc[2 * nv], ah, bh);
                mma_bf16(acc[2 * nv], ah, bl);
                mma_bf16(acc[2 * nv], al, bh);
                mma_bf16(acc[2 * nv + 1], ah, bh + 2);
                mma_bf16(acc[2 * nv + 1], ah, bl + 2);
                mma_bf16(acc[2 * nv + 1], al, bh + 2);
            }
        }
        __syncthreads();
    }

    float* P = g_Pp + (long)ksplit * (BATCH * SEQ * DIM);
    const int mr0 = m0 + m0w + (lane >> 2);
#pragma unroll
    for (int t = 0; t < 16; t++) {
        int col = t * 8 + ((lane & 3) << 1);
        *(float2*)(P + (long)mr0 * 128 + col) = make_float2(acc[t][0], acc[t][1]);
        *(float2*)(P + (long)(mr0 + 8) * 128 + col) = make_float2(acc[t][2], acc[t][3]);
    }
}

// ---------------------------------------------------------------------------
// Kernel D: reduce 4 partials -> out (fixed order, deterministic)
// ---------------------------------------------------------------------------
#define NOUT4 (BATCH * SEQ * DIM / 4)   // 262144
__global__ void __launch_bounds__(256) proj_reduce_kernel(float* __restrict__ out) {
    int i = blockIdx.x * 256 + threadIdx.x;
    if (i >= NOUT4) return;
    const long stride = (long)BATCH * SEQ * DIM;
    float4 a = *(const float4*)(g_Pp + 4 * (long)i);
    float4 b = *(const float4*)(g_Pp + stride + 4 * (long)i);
    float4 c = *(const float4*)(g_Pp + 2 * stride + 4 * (long)i);
    float4 d = *(const float4*)(g_Pp + 3 * stride + 4 * (long)i);
    float4 r;
    r.x = (a.x + b.x) + (c.x + d.x);
    r.y = (a.y + b.y) + (c.y + d.y);
    r.z = (a.z + b.z) + (c.z + d.z);
    r.w = (a.w + b.w) + (c.w + d.w);
    *(float4*)(out + 4 * (long)i) = r;
}

// ---------------------------------------------------------------------------
extern "C" void kernel_launch(void* const* d_in, const int* in_sizes, int n_in,
                              void* d_out, int out_size) {
    const float* x     = (const float*)d_in[0];
    const float* Wqkv  = (const float*)d_in[1];
    const float* Wproj = (const float*)d_in[2];
    float* out = (float*)d_out;

    prep_kernel<<<(NPX + NPQ + NPP + 255) / 256, 256>>>(x, Wqkv, Wproj);

    cudaFuncSetAttribute(qkv_kernel, cudaFuncAttributeMaxDynamicSharedMemorySize, QKV_SMEM);
    qkv_kernel<<<dim3(8192 / 128, 24), 256, QKV_SMEM>>>();

    cudaFuncSetAttribute(attn_kernel, cudaFuncAttributeMaxDynamicSharedMemorySize, ATTN_SMEM);
    attn_kernel<<<dim3(SEQ / 128, QH, BATCH), 256, ATTN_SMEM>>>();

    cudaFuncSetAttribute(proj_partial_kernel, cudaFuncAttributeMaxDynamicSharedMemorySize, PROJ_SMEM);
    proj_partial_kernel<<<dim3(8192 / 64, 4), 128, PROJ_SMEM>>>();

    proj_reduce_kernel<<<(NOUT4 + 255) / 256, 256>>>(out);
}

// round 8
// speedup vs baseline: 4.7605x; 1.0649x over previous
#include <cuda_runtime.h>
#include <cuda_bf16.h>
#include <cstdint>
#include <math.h>

#define BATCH 4
#define SEQ 2048
#define DIM 128
#define QH 16
#define KVH 4
#define WINDOW 512

// ---------------------------------------------------------------------------
// device-global scratch (allocation-free)
// ---------------------------------------------------------------------------
__device__ __nv_bfloat16 g_Xh[BATCH * SEQ * DIM];
__device__ __nv_bfloat16 g_Xl[BATCH * SEQ * DIM];
__device__ __nv_bfloat16 g_Wqh[DIM * 3072];
__device__ __nv_bfloat16 g_Wql[DIM * 3072];
__device__ __nv_bfloat16 g_Wph[2048 * DIM];
__device__ __nv_bfloat16 g_Wpl[2048 * DIM];
__device__ __nv_bfloat16 g_Qh[BATCH * QH * SEQ * DIM];
__device__ __nv_bfloat16 g_Ql[BATCH * QH * SEQ * DIM];
__device__ __nv_bfloat16 g_Kh[BATCH * KVH * SEQ * DIM];
__device__ __nv_bfloat16 g_Kl[BATCH * KVH * SEQ * DIM];
__device__ __nv_bfloat16 g_Vh[BATCH * KVH * SEQ * DIM];
__device__ __nv_bfloat16 g_Vl[BATCH * KVH * SEQ * DIM];
__device__ __nv_bfloat16 g_Ah[BATCH * SEQ * QH * DIM];
__device__ __nv_bfloat16 g_Al[BATCH * SEQ * QH * DIM];
__device__ float g_Pp[4 * BATCH * SEQ * DIM];

// ---------------------------------------------------------------------------
// base-ISA helpers
// ---------------------------------------------------------------------------
__device__ __forceinline__ uint32_t smem_u32(const void* p) {
    uint32_t a;
    asm("{ .reg .u64 t; cvta.to.shared.u64 t, %1; cvt.u32.u64 %0, t; }" : "=r"(a) : "l"(p));
    return a;
}
__device__ __forceinline__ void ldm_x4(uint32_t* r, uint32_t addr) {
    asm volatile("ldmatrix.sync.aligned.m8n8.x4.shared.b16 {%0,%1,%2,%3},[%4];"
        : "=r"(r[0]), "=r"(r[1]), "=r"(r[2]), "=r"(r[3]) : "r"(addr));
}
__device__ __forceinline__ void ldm_x4t(uint32_t* r, uint32_t addr) {
    asm volatile("ldmatrix.sync.aligned.m8n8.x4.trans.shared.b16 {%0,%1,%2,%3},[%4];"
        : "=r"(r[0]), "=r"(r[1]), "=r"(r[2]), "=r"(r[3]) : "r"(addr));
}
__device__ __forceinline__ void mma_bf16(float* d, const uint32_t* a, const uint32_t* b) {
    asm volatile(
        "mma.sync.aligned.m16n8k16.row.col.f32.bf16.bf16.f32 "
        "{%0,%1,%2,%3},{%4,%5,%6,%7},{%8,%9},{%0,%1,%2,%3};"
        : "+f"(d[0]), "+f"(d[1]), "+f"(d[2]), "+f"(d[3])
        : "r"(a[0]), "r"(a[1]), "r"(a[2]), "r"(a[3]), "r"(b[0]), "r"(b[1]));
}
__device__ __forceinline__ uint32_t pkbf(float lo, float hi) {
    uint32_t r; asm("cvt.rn.bf16x2.f32 %0,%1,%2;" : "=r"(r) : "f"(hi), "f"(lo)); return r;
}
__device__ __forceinline__ float btrunc(float x) {
    return __uint_as_float(__float_as_uint(x) & 0xffff0000u);
}
__device__ __forceinline__ float ex2(float x) {
    float y; asm("ex2.approx.ftz.f32 %0,%1;" : "=f"(y) : "f"(x)); return y;
}
__device__ __forceinline__ void cp16(uint32_t dst, const void* src) {
    asm volatile("cp.async.cg.shared.global [%0], [%1], 16;" :: "r"(dst), "l"(src));
}
__device__ __forceinline__ void cp_commit() { asm volatile("cp.async.commit_group;"); }
template <int N> __device__ __forceinline__ void cp_wait() {
    asm volatile("cp.async.wait_group %0;" :: "n"(N));
}
__device__ __forceinline__ void split2(float v0, float v1, uint32_t& hp, uint32_t& lp) {
    hp = pkbf(v0, v1);
    float h0 = __uint_as_float(hp << 16);
    float h1 = __uint_as_float(hp & 0xffff0000u);
    lp = pkbf(v0 - h0, v1 - h1);
}

// ---------------------------------------------------------------------------
// Kernel 0: split inputs into bf16 hi/lo
// ---------------------------------------------------------------------------
#define NPX (BATCH * SEQ * DIM / 2)
#define NPQ (DIM * 3072 / 2)
#define NPP (2048 * DIM / 2)
__global__ void __launch_bounds__(256) prep_kernel(const float* __restrict__ x,
                                                   const float* __restrict__ Wqkv,
                                                   const float* __restrict__ Wproj) {
    const float qscale = 1.4426950408889634f * 0.08838834764831845f;
    int i = blockIdx.x * 256 + threadIdx.x;
    if (i < NPX) {
        float2 v = *(const float2*)(x + 2 * i);
        uint32_t hp, lp; split2(v.x, v.y, hp, lp);
        *(uint32_t*)(g_Xh + 2 * i) = hp; *(uint32_t*)(g_Xl + 2 * i) = lp;
    } else if (i < NPX + NPQ) {
        int j = i - NPX;
        float2 v = *(const float2*)(Wqkv + 2 * j);
        int col = (2 * j) % 3072;
        if (col < QH * DIM) { v.x *= qscale; v.y *= qscale; }
        uint32_t hp, lp; split2(v.x, v.y, hp, lp);
        *(uint32_t*)(g_Wqh + 2 * j) = hp; *(uint32_t*)(g_Wql + 2 * j) = lp;
    } else if (i < NPX + NPQ + NPP) {
        int j = i - NPX - NPQ;
        float2 v = *(const float2*)(Wproj + 2 * j);
        uint32_t hp, lp; split2(v.x, v.y, hp, lp);
        *(uint32_t*)(g_Wph + 2 * j) = hp; *(uint32_t*)(g_Wpl + 2 * j) = lp;
    }
}

// ---------------------------------------------------------------------------
// Kernel A: qkv via HMMA, 2-phase k-pipelined loads
// ---------------------------------------------------------------------------
#define TSTR_B 272
#define QKV_TILE (128 * TSTR_B)
#define QKV_SMEM (4 * QKV_TILE)

__global__ void __launch_bounds__(256) qkv_kernel() {
    extern __shared__ char smc[];
    const uint32_t sb = smem_u32(smc);
    const int tid = threadIdx.x;
    const int lane = tid & 31;
    const int w = tid >> 5;
    const int m0w = w * 16;
    const int m0 = blockIdx.x * 128;
    const int head = blockIdx.y;
    const int n0 = head * 128;

    for (int idx = tid; idx < 4096; idx += 256) {
        if (idx < 2048) {
            int arr = idx >> 10, r = (idx >> 3) & 127, c = idx & 7;
            const char* src = (const char*)(arr ? g_Xl : g_Xh) + (long)(m0 + r) * 256 + c * 16;
            cp16(sb + arr * QKV_TILE + r * TSTR_B + c * 16, src);
        } else {
            int j = idx - 2048;
            int arr = j >> 10, r = (j >> 4) & 63, c = j & 15;
            const char* src = (const char*)(arr ? g_Wql : g_Wqh) + ((long)r * 3072 + n0) * 2 + c * 16;
            cp16(sb + (2 + arr) * QKV_TILE + r * TSTR_B + c * 16, src);
        }
    }
    cp_commit();
    for (int idx = tid; idx < 4096; idx += 256) {
        if (idx < 2048) {
            int arr = idx >> 10, r = (idx >> 3) & 127, c = (idx & 7) + 8;
            const char* src = (const char*)(arr ? g_Xl : g_Xh) + (long)(m0 + r) * 256 + c * 16;
            cp16(sb + arr * QKV_TILE + r * TSTR_B + c * 16, src);
        } else {
            int j = idx - 2048;
            int arr = j >> 10, r = ((j >> 4) & 63) + 64, c = j & 15;
            const char* src = (const char*)(arr ? g_Wql : g_Wqh) + ((long)r * 3072 + n0) * 2 + c * 16;
            cp16(sb + (2 + arr) * QKV_TILE + r * TSTR_B + c * 16, src);
        }
    }
    cp_commit();

    const uint32_t XH = sb, XL = sb + QKV_TILE;
    const uint32_t WH = sb + 2 * QKV_TILE, WL = sb + 3 * QKV_TILE;
    const uint32_t aoff = (uint32_t)(m0w + (lane & 15)) * TSTR_B + ((lane >> 4) << 3) * 2;
    const uint32_t voff = (uint32_t)((lane & 8) + (lane & 7)) * TSTR_B + ((lane >> 4) << 3) * 2;

    float acc[16][4];
#pragma unroll
    for (int t = 0; t < 16; t++)
#pragma unroll
        for (int j = 0; j < 4; j++) acc[t][j] = 0.0f;

#pragma unroll
    for (int ph = 0; ph < 2; ph++) {
        if (ph == 0) cp_wait<1>(); else cp_wait<0>();
        __syncthreads();
#pragma unroll
        for (int ks2 = 0; ks2 < 4; ks2++) {
            int ks = ph * 4 + ks2;
            uint32_t ah[4], al[4];
            ldm_x4(ah, XH + aoff + ks * 32);
            ldm_x4(al, XL + aoff + ks * 32);
            uint32_t vbase = voff + (uint32_t)(ks * 16) * TSTR_B;
#pragma unroll
            for (int nv = 0; nv < 8; nv++) {
                uint32_t bh[4], bl[4];
                ldm_x4t(bh, WH + vbase + nv * 32);
                ldm_x4t(bl, WL + vbase + nv * 32);
                mma_bf16(acc[2 * nv], ah, bh);
                mma_bf16(acc[2 * nv], ah, bl);
                mma_bf16(acc[2 * nv], al, bh);
                mma_bf16(acc[2 * nv + 1], ah, bh + 2);
                mma_bf16(acc[2 * nv + 1], ah, bl + 2);
                mma_bf16(acc[2 * nv + 1], al, bh + 2);
            }
        }
    }

    __nv_bfloat16 *dh, *dl;
    int hh, nheads;
    if (head < QH)            { dh = g_Qh; dl = g_Ql; hh = head;            nheads = QH; }
    else if (head < QH + KVH) { dh = g_Kh; dl = g_Kl; hh = head - QH;       nheads = KVH; }
    else                      { dh = g_Vh; dl = g_Vl; hh = head - QH - KVH; nheads = KVH; }

    const int mr0 = m0 + m0w + (lane >> 2);
#pragma unroll
    for (int half = 0; half < 2; half++) {
        int m = mr0 + half * 8;
        int b = m >> 11, s = m & 2047;
        long rowo = ((long)(b * nheads + hh) * SEQ + s) * DIM + ((lane & 3) << 1);
#pragma unroll
        for (int t = 0; t < 16; t++) {
            uint32_t hp, lp;
            split2(acc[t][2 * half], acc[t][2 * half + 1], hp, lp);
            *(uint32_t*)(dh + rowo + t * 8) = hp;
            *(uint32_t*)(dl + rowo + t * 8) = lp;
        }
    }
}

// ---------------------------------------------------------------------------
// Kernel B: flash attention + warp-level dead-tile skip + reversed qt order
// ---------------------------------------------------------------------------
#define Q_BYTES (128 * TSTR_B)
#define KV_TILE_B (64 * TSTR_B)
#define STAGE_B (4 * KV_TILE_B)
#define ST_OFF (2 * Q_BYTES)
#define ATTN_SMEM (ST_OFF + 2 * STAGE_B)

__global__ void __launch_bounds__(256) attn_kernel() {
    extern __shared__ char smc[];
    const uint32_t sb = smem_u32(smc);
    const int tid = threadIdx.x;
    const int lane = tid & 31;
    const int w = tid >> 5;
    const int m0w = w * 16;

    const int qt = (SEQ / 128 - 1) - blockIdx.x;   // big blocks first
    const int h  = blockIdx.y;
    const int b  = blockIdx.z;
    const int g  = h >> 2;
    const int q0 = qt * 128;
    const float slope2 = exp2f(-(float)(h + 1) * 0.5f) * 1.4426950408889634f;

    const __nv_bfloat16* Qhg = g_Qh + ((long)(b * QH + h) * SEQ + q0) * DIM;
    const __nv_bfloat16* Qlg = g_Ql + ((long)(b * QH + h) * SEQ + q0) * DIM;
    const __nv_bfloat16* Khg = g_Kh + (long)(b * KVH + g) * SEQ * DIM;
    const __nv_bfloat16* Klg = g_Kl + (long)(b * KVH + g) * SEQ * DIM;
    const __nv_bfloat16* Vhg = g_Vh + (long)(b * KVH + g) * SEQ * DIM;
    const __nv_bfloat16* Vlg = g_Vl + (long)(b * KVH + g) * SEQ * DIM;

    const int ktlo = (q0 >= WINDOW) ? (q0 - WINDOW) : 0;
    const int nt = (q0 + 128 - ktlo) >> 6;

    for (int idx = tid; idx < 4096; idx += 256) {
        int arr = idx >> 11, r = (idx >> 4) & 127, c = idx & 15;
        const char* src = (const char*)(arr ? Qlg : Qhg) + r * 256 + c * 16;
        cp16(sb + arr * Q_BYTES + r * TSTR_B + c * 16, src);
    }
    {
        const __nv_bfloat16* srcs[4] = { Khg, Klg, Vhg, Vlg };
        for (int idx = tid; idx < 4096; idx += 256) {
            int arr = idx >> 10, r = (idx >> 4) & 63, c = idx & 15;
            cp16(sb + ST_OFF + arr * KV_TILE_B + r * TSTR_B + c * 16,
                 (const char*)srcs[arr] + (long)(ktlo + r) * 256 + c * 16);
        }
    }
    cp_commit();

    float m0r = -1e30f, m1r = -1e30f, l0 = 0.0f, l1 = 0.0f;
    float oacc[16][4];
#pragma unroll
    for (int t = 0; t < 16; t++)
#pragma unroll
        for (int j = 0; j < 4; j++) oacc[t][j] = 0.0f;

    const int qr0 = q0 + m0w + (lane >> 2);
    const int qr1 = qr0 + 8;
    const int wq_lo = q0 + m0w;          // warp's lowest q row
    const int wq_hi = q0 + m0w + 15;     // warp's highest q row

    const uint32_t aoff = (uint32_t)(m0w + (lane & 15)) * TSTR_B + ((lane >> 4) << 3) * 2;
    const uint32_t boff_n = (uint32_t)(((lane >> 4) << 3) + (lane & 7)) * TSTR_B + (lane & 8) * 2;
    const uint32_t voff_r = (uint32_t)((lane & 8) + (lane & 7)) * TSTR_B + ((lane >> 4) << 3) * 2;

    for (int it = 0; it < nt; it++) {
        const int kt = ktlo + it * 64;
        const int st = it & 1;

        if (it + 1 < nt) {
            const int ktn = kt + 64;
            const uint32_t dstb = sb + ST_OFF + (st ^ 1) * STAGE_B;
            const __nv_bfloat16* srcs[4] = { Khg, Klg, Vhg, Vlg };
            for (int idx = tid; idx < 4096; idx += 256) {
                int arr = idx >> 10, r = (idx >> 4) & 63, c = idx & 15;
                cp16(dstb + arr * KV_TILE_B + r * TSTR_B + c * 16,
                     (const char*)srcs[arr] + (long)(ktn + r) * 256 + c * 16);
            }
            cp_commit();
            cp_wait<1>();
        } else {
            cp_wait<0>();
        }
        __syncthreads();

        // warp-level dead-tile skip (warp-uniform condition; exact: all P == 0)
        const bool act = (kt <= wq_hi) && (kt + 63 >= wq_lo - WINDOW);
        if (act) {
            const uint32_t kb = sb + ST_OFF + st * STAGE_B;
            const uint32_t KHO = kb, KLO = kb + KV_TILE_B;
            const uint32_t VHO = kb + 2 * KV_TILE_B, VLO = kb + 3 * KV_TILE_B;

            float sacc[8][4];
#pragma unroll
            for (int t = 0; t < 8; t++)
#pragma unroll
                for (int j = 0; j < 4; j++) sacc[t][j] = 0.0f;

#pragma unroll
            for (int ks = 0; ks < 8; ks++) {
                uint32_t ah[4], al[4];
                ldm_x4(ah, sb + aoff + ks * 32);
                ldm_x4(al, sb + Q_BYTES + aoff + ks * 32);
#pragma unroll
                for (int ntl = 0; ntl < 4; ntl++) {
                    uint32_t bh[4], bl[4];
                    uint32_t bo = boff_n + (uint32_t)(ntl * 16) * TSTR_B + ks * 32;
                    ldm_x4(bh, KHO + bo);
                    ldm_x4(bl, KLO + bo);
                    mma_bf16(sacc[2 * ntl], ah, bh);
                    mma_bf16(sacc[2 * ntl], ah, bl);
                    mma_bf16(sacc[2 * ntl], al, bh);
                    mma_bf16(sacc[2 * ntl + 1], ah, bh + 2);
                    mma_bf16(sacc[2 * ntl + 1], ah, bl + 2);
                    mma_bf16(sacc[2 * ntl + 1], al, bh + 2);
                }
            }

#pragma unroll
            for (int t = 0; t < 8; t++) {
                int c0 = kt + t * 8 + ((lane & 3) << 1);
                int c1 = c0 + 1;
                int d00 = qr0 - c0, d01 = qr0 - c1, d10 = qr1 - c0, d11 = qr1 - c1;
                sacc[t][0] = (d00 >= 0 && d00 <= WINDOW) ? sacc[t][0] + slope2 * (float)d00 : -1e32f;
                sacc[t][1] = (d01 >= 0 && d01 <= WINDOW) ? sacc[t][1] + slope2 * (float)d01 : -1e32f;
                sacc[t][2] = (d10 >= 0 && d10 <= WINDOW) ? sacc[t][2] + slope2 * (float)d10 : -1e32f;
                sacc[t][3] = (d11 >= 0 && d11 <= WINDOW) ? sacc[t][3] + slope2 * (float)d11 : -1e32f;
            }

            float mx0 = -1e32f, mx1 = -1e32f;
#pragma unroll
            for (int t = 0; t < 8; t++) {
                mx0 = fmaxf(mx0, fmaxf(sacc[t][0], sacc[t][1]));
                mx1 = fmaxf(mx1, fmaxf(sacc[t][2], sacc[t][3]));
            }
            mx0 = fmaxf(mx0, __shfl_xor_sync(0xffffffffu, mx0, 1));
            mx0 = fmaxf(mx0, __shfl_xor_sync(0xffffffffu, mx0, 2));
            mx1 = fmaxf(mx1, __shfl_xor_sync(0xffffffffu, mx1, 1));
            mx1 = fmaxf(mx1, __shfl_xor_sync(0xffffffffu, mx1, 2));
            float mn0 = fmaxf(m0r, mx0), mn1 = fmaxf(m1r, mx1);
            float a0 = ex2(m0r - mn0), a1 = ex2(m1r - mn1);
            m0r = mn0; m1r = mn1;

            float ps0 = 0.0f, ps1 = 0.0f;
#pragma unroll
            for (int t = 0; t < 8; t++) {
                sacc[t][0] = ex2(sacc[t][0] - mn0);
                sacc[t][1] = ex2(sacc[t][1] - mn0);
                sacc[t][2] = ex2(sacc[t][2] - mn1);
                sacc[t][3] = ex2(sacc[t][3] - mn1);
                ps0 += sacc[t][0] + sacc[t][1];
                ps1 += sacc[t][2] + sacc[t][3];
            }
            l0 = l0 * a0 + ps0;
            l1 = l1 * a1 + ps1;
#pragma unroll
            for (int t = 0; t < 16; t++) {
                oacc[t][0] *= a0; oacc[t][1] *= a0;
                oacc[t][2] *= a1; oacc[t][3] *= a1;
            }

#pragma unroll
            for (int kp = 0; kp < 4; kp++) {
                const float* s0 = sacc[2 * kp];
                const float* s1 = sacc[2 * kp + 1];
                uint32_t aPh[4], aPl[4];
                aPh[0] = __byte_perm(__float_as_uint(s0[0]), __float_as_uint(s0[1]), 0x7632);
                aPh[1] = __byte_perm(__float_as_uint(s0[2]), __float_as_uint(s0[3]), 0x7632);
                aPh[2] = __byte_perm(__float_as_uint(s1[0]), __float_as_uint(s1[1]), 0x7632);
                aPh[3] = __byte_perm(__float_as_uint(s1[2]), __float_as_uint(s1[3]), 0x7632);
                aPl[0] = pkbf(s0[0] - btrunc(s0[0]), s0[1] - btrunc(s0[1]));
                aPl[1] = pkbf(s0[2] - btrunc(s0[2]), s0[3] - btrunc(s0[3]));
                aPl[2] = pkbf(s1[0] - btrunc(s1[0]), s1[1] - btrunc(s1[1]));
                aPl[3] = pkbf(s1[2] - btrunc(s1[2]), s1[3] - btrunc(s1[3]));

                uint32_t vbase = voff_r + (uint32_t)(kp * 16) * TSTR_B;
#pragma unroll
                for (int nv = 0; nv < 8; nv++) {
                    uint32_t bvh[4], bvl[4];
                    uint32_t vo = vbase + nv * 32;
                    ldm_x4t(bvh, VHO + vo);
                    ldm_x4t(bvl, VLO + vo);
                    mma_bf16(oacc[2 * nv], aPh, bvh);
                    mma_bf16(oacc[2 * nv], aPh, bvl);
                    mma_bf16(oacc[2 * nv], aPl, bvh);
                    mma_bf16(oacc[2 * nv + 1], aPh, bvh + 2);
                    mma_bf16(oacc[2 * nv + 1], aPh, bvl + 2);
                    mma_bf16(oacc[2 * nv + 1], aPl, bvh + 2);
                }
            }
        }
        __syncthreads();
    }

    l0 += __shfl_xor_sync(0xffffffffu, l0, 1);
    l0 += __shfl_xor_sync(0xffffffffu, l0, 2);
    l1 += __shfl_xor_sync(0xffffffffu, l1, 1);
    l1 += __shfl_xor_sync(0xffffffffu, l1, 2);
    const float i0 = 1.0f / l0, i1 = 1.0f / l1;

    long r0 = ((long)b * SEQ + qr0) * (QH * DIM) + h * DIM + ((lane & 3) << 1);
    long r1 = ((long)b * SEQ + qr1) * (QH * DIM) + h * DIM + ((lane & 3) << 1);
#pragma unroll
    for (int t = 0; t < 16; t++) {
        uint32_t hp, lp;
        split2(oacc[t][0] * i0, oacc[t][1] * i0, hp, lp);
        *(uint32_t*)(g_Ah + r0 + t * 8) = hp;
        *(uint32_t*)(g_Al + r0 + t * 8) = lp;
        split2(oacc[t][2] * i1, oacc[t][3] * i1, hp, lp);
        *(uint32_t*)(g_Ah + r1 + t * 8) = hp;
        *(uint32_t*)(g_Al + r1 + t * 8) = lp;
    }
}

// ---------------------------------------------------------------------------
// Kernel C: proj split-K partials. Single-buffered stage -> 4 CTAs/SM.
// ---------------------------------------------------------------------------
#define ASTR_B 144
#define PA_TILE (64 * ASTR_B)
#define PW_TILE (64 * TSTR_B)
#define PSTAGE (2 * PA_TILE + 2 * PW_TILE)   // 53248
#define PROJ_SMEM PSTAGE

__global__ void __launch_bounds__(128) proj_partial_kernel() {
    extern __shared__ char smc[];
    const uint32_t sb = smem_u32(smc);
    const int tid = threadIdx.x;
    const int lane = tid & 31;
    const int w = tid >> 5;
    const int m0w = w * 16;
    const int m0 = blockIdx.x * 64;
    const int ksplit = blockIdx.y;
    const int kbase = ksplit * 512;

    auto load_chunk = [&](int k0) {
        for (int idx = tid; idx < 3072; idx += 128) {
            if (idx < 1024) {
                int arr = idx >> 9, r = (idx >> 3) & 63, c = idx & 7;
                const char* src = (const char*)(arr ? g_Al : g_Ah) +
                                  (long)(m0 + r) * 4096 + k0 * 2 + c * 16;
                cp16(sb + arr * PA_TILE + r * ASTR_B + c * 16, src);
            } else {
                int j = idx - 1024;
                int arr = j >> 10, r = (j >> 4) & 63, c = j & 15;
                const char* src = (const char*)(arr ? g_Wpl : g_Wph) +
                                  (long)(k0 + r) * 256 + c * 16;
                cp16(sb + 2 * PA_TILE + arr * PW_TILE + r * TSTR_B + c * 16, src);
            }
        }
    };

    const uint32_t aoffA = (uint32_t)(m0w + (lane & 15)) * ASTR_B + ((lane >> 4) << 3) * 2;
    const uint32_t voffW = (uint32_t)((lane & 8) + (lane & 7)) * TSTR_B + ((lane >> 4) << 3) * 2;

    float acc[16][4];
#pragma unroll
    for (int t = 0; t < 16; t++)
#pragma unroll
        for (int j = 0; j < 4; j++) acc[t][j] = 0.0f;

    for (int it = 0; it < 8; it++) {
        load_chunk(kbase + it * 64);
        cp_commit();
        cp_wait<0>();
        __syncthreads();

        const uint32_t AH = sb, AL = sb + PA_TILE;
        const uint32_t WH = sb + 2 * PA_TILE, WL = WH + PW_TILE;

#pragma unroll
        for (int ks = 0; ks < 4; ks++) {
            uint32_t ah[4], al[4];
            ldm_x4(ah, AH + aoffA + ks * 32);
            ldm_x4(al, AL + aoffA + ks * 32);
            uint32_t vbase = voffW + (uint32_t)(ks * 16) * TSTR_B;
#pragma unroll
            for (int nv = 0; nv < 8; nv++) {
                uint32_t bh[4], bl[4];
                ldm_x4t(bh, WH + vbase + nv * 32);
                ldm_x4t(bl, WL + vbase + nv * 32);
                mma_bf16(acc[2 * nv], ah, bh);
                mma_bf16(acc[2 * nv], ah, bl);
                mma_bf16(acc[2 * nv], al, bh);
                mma_bf16(acc[2 * nv + 1], ah, bh + 2);
                mma_bf16(acc[2 * nv + 1], ah, bl + 2);
                mma_bf16(acc[2 * nv + 1], al, bh + 2);
            }
        }
        __syncthreads();
    }

    float* P = g_Pp + (long)ksplit * (BATCH * SEQ * DIM);
    const int mr0 = m0 + m0w + (lane >> 2);
#pragma unroll
    for (int t = 0; t < 16; t++) {
        int col = t * 8 + ((lane & 3) << 1);
        *(float2*)(P + (long)mr0 * 128 + col) = make_float2(acc[t][0], acc[t][1]);
        *(float2*)(P + (long)(mr0 + 8) * 128 + col) = make_float2(acc[t][2], acc[t][3]);
    }
}

// ---------------------------------------------------------------------------
// Kernel D: reduce 4 partials -> out (fixed order, deterministic)
// ---------------------------------------------------------------------------
#define NOUT4 (BATCH * SEQ * DIM / 4)
__global__ void __launch_bounds__(256) proj_reduce_kernel(float* __restrict__ out) {
    int i = blockIdx.x * 256 + threadIdx.x;
    if (i >= NOUT4) return;
    const long stride = (long)BATCH * SEQ * DIM;
    float4 a = *(const float4*)(g_Pp + 4 * (long)i);
    float4 b = *(const float4*)(g_Pp + stride + 4 * (long)i);
    float4 c = *(const float4*)(g_Pp + 2 * stride + 4 * (long)i);
    float4 d = *(const float4*)(g_Pp + 3 * stride + 4 * (long)i);
    float4 r;
    r.x = (a.x + b.x) + (c.x + d.x);
    r.y = (a.y + b.y) + (c.y + d.y);
    r.z = (a.z + b.z) + (c.z + d.z);
    r.w = (a.w + b.w) + (c.w + d.w);
    *(float4*)(out + 4 * (long)i) = r;
}

// ---------------------------------------------------------------------------
extern "C" void kernel_launch(void* const* d_in, const int* in_sizes, int n_in,
                              void* d_out, int out_size) {
    const float* x     = (const float*)d_in[0];
    const float* Wqkv  = (const float*)d_in[1];
    const float* Wproj = (const float*)d_in[2];
    float* out = (float*)d_out;

    prep_kernel<<<(NPX + NPQ + NPP + 255) / 256, 256>>>(x, Wqkv, Wproj);

    cudaFuncSetAttribute(qkv_kernel, cudaFuncAttributeMaxDynamicSharedMemorySize, QKV_SMEM);
    qkv_kernel<<<dim3(8192 / 128, 24), 256, QKV_SMEM>>>();

    cudaFuncSetAttribute(attn_kernel, cudaFuncAttributeMaxDynamicSharedMemorySize, ATTN_SMEM);
    attn_kernel<<<dim3(SEQ / 128, QH, BATCH), 256, ATTN_SMEM>>>();

    cudaFuncSetAttribute(proj_partial_kernel, cudaFuncAttributeMaxDynamicSharedMemorySize, PROJ_SMEM);
    proj_partial_kernel<<<dim3(8192 / 64, 4), 128, PROJ_SMEM>>>();

    proj_reduce_kernel<<<(NOUT4 + 255) / 256, 256>>>(out);
}